// round 13
// baseline (speedup 1.0000x reference)
#include <cuda_runtime.h>
#include <cuda_fp16.h>
#include <cstdint>

#define HWSZ  65536
#define CDIM  192
#define NHEADS 8
#define CH    24
#define BSZ   2
#define QP2   260

// ---------------- scratch (no cudaMalloc allowed) ----------------
__device__ float  g_pre [(size_t)BSZ * 3 * CDIM * HWSZ];   // q (nt0) + kv (nt1,2)
__device__ __half g_vh  [(size_t)BSZ * CDIM     * HWSZ];   // v in fp16
__device__ float  g_gram[BSZ * NHEADS * CH * CH];
__device__ float  g_ssq [BSZ * CDIM];
__device__ float  g_ssk [BSZ * CDIM];
__device__ float  g_M   [BSZ * CDIM * CDIM];

// fp16 weights: slot 0 = wq, slots 1,2 = wkv   (row-major [rows][192])
__device__ __half g_wqkv[3 * CDIM * CDIM];
__device__ __half g_whm [BSZ * CDIM * CDIM];

__device__ __forceinline__ uint32_t smem_u32(const void* p) {
    uint32_t a;
    asm("{ .reg .u64 t; cvta.to.shared.u64 t, %1; cvt.u32.u64 %0, t; }" : "=r"(a) : "l"(p));
    return a;
}
__device__ __forceinline__ void cpa16(uint32_t dst, const void* src) {
    asm volatile("cp.async.cg.shared.global [%0], [%1], 16;" :: "r"(dst), "l"(src));
}
#define CPA_COMMIT() asm volatile("cp.async.commit_group;" ::: "memory")
#define CPA_WAIT(n)  asm volatile("cp.async.wait_group %0;" :: "n"(n) : "memory")

// ---------------- zero accumulators ----------------
__global__ void zero_stats_kernel(float* gram, float* ssq, float* ssk) {
    int i = blockIdx.x * 256 + threadIdx.x;
    if (i < BSZ * NHEADS * CH * CH) gram[i] = 0.f;
    if (i < BSZ * CDIM) { ssq[i] = 0.f; ssk[i] = 0.f; }
}

// ---------------- prep: fp32 W -> fp16 ----------------
__global__ void w2f16_kernel(const float* __restrict__ W, long long wstride_b,
                             int total, __half* __restrict__ out, long long ostride_b) {
    int b = blockIdx.z;
    int i = blockIdx.x * 256 + threadIdx.x;
    if (i >= total) return;
    out[(size_t)b * ostride_b + i] = __float2half_rn(W[(size_t)b * wstride_b + i]);
}

// ================= pipelined HMMA fp16 2-pass GEMM, BK=32 (fp32 X) =================
#define AST 40
#define BST 72
#define OFF_W(s)  ((s) * 7680)
#define OFF_XH(s) (23040 + (s) * 4608)
#define OFF_XL(s) (23040 + (s) * 4608 + 2304)
#define GEMM_SMEM (32256 * 2)

__global__ __launch_bounds__(256, 2) void hmma_gemm_kernel(
    const float* __restrict__ X, long long xstride_b,
    const __half* __restrict__ Wh, long long wstride_b,
    float* __restrict__ Y, long long ystride_b)
{
    extern __shared__ __half sms[];
    const uint32_t sb = smem_u32(sms);

    const int tid = threadIdx.x;
    const int lid = tid & 31;
    const int wid = tid >> 5;
    const int wm  = wid >> 1;
    const int wn  = wid & 1;
    const int p0  = blockIdx.x * 64;
    const int nt  = blockIdx.y;
    const int b   = blockIdx.z;

    const float* Xb = X + (size_t)b * xstride_b + p0;
    const __half* WhB = Wh + (size_t)b * wstride_b + (size_t)nt * 192 * 192;

    float acc[3][4][4];
#pragma unroll
    for (int i = 0; i < 3; i++)
#pragma unroll
        for (int j = 0; j < 4; j++)
#pragma unroll
            for (int r = 0; r < 4; r++) acc[i][j][r] = 0.f;

    const int xrow = tid >> 4, xc4 = (tid & 15) << 2;
    const int arow = (lid & 7) + ((lid >> 3) & 1) * 8;
    const int acol = (lid >> 4) * 8;
    const int brow = arow;
    const int bcoff = ((lid >> 4) & 1) * 8;

#pragma unroll
    for (int s = 0; s < 2; s++) {
#pragma unroll
        for (int j = 0; j < 3; j++) {
            int idx = tid + j * 256;
            int row = idx >> 2;
            int c8  = (idx & 3) << 3;
            cpa16(sb + (uint32_t)((OFF_W(s) + row * AST + c8) * 2),
                  WhB + (size_t)row * 192 + s * 32 + c8);
        }
        CPA_COMMIT();
    }
    float4 xv0 = *reinterpret_cast<const float4*>(Xb + (size_t)xrow * HWSZ + xc4);
    float4 xv1 = *reinterpret_cast<const float4*>(Xb + (size_t)(xrow + 16) * HWSZ + xc4);

#pragma unroll 1
    for (int it = 0; it < 6; it++) {
        const int ws = it % 3;
        const int xs = it & 1;

#pragma unroll
        for (int hlf = 0; hlf < 2; hlf++) {
            float4 v = hlf ? xv1 : xv0;
            int row = xrow + hlf * 16;
            __half hx = __float2half_rn(v.x), hy = __float2half_rn(v.y);
            __half hz = __float2half_rn(v.z), hw = __float2half_rn(v.w);
            uint32_t h01 = (uint32_t)__half_as_ushort(hx)
                         | ((uint32_t)__half_as_ushort(hy) << 16);
            uint32_t h23 = (uint32_t)__half_as_ushort(hz)
                         | ((uint32_t)__half_as_ushort(hw) << 16);
            __half lx = __float2half_rn(v.x - __half2float(hx));
            __half ly = __float2half_rn(v.y - __half2float(hy));
            __half lz = __float2half_rn(v.z - __half2float(hz));
            __half lw = __float2half_rn(v.w - __half2float(hw));
            uint32_t l01 = (uint32_t)__half_as_ushort(lx)
                         | ((uint32_t)__half_as_ushort(ly) << 16);
            uint32_t l23 = (uint32_t)__half_as_ushort(lz)
                         | ((uint32_t)__half_as_ushort(lw) << 16);
            uint32_t xh = sb + (uint32_t)((OFF_XH(xs) + row * BST + xc4) * 2);
            uint32_t xl = sb + (uint32_t)((OFF_XL(xs) + row * BST + xc4) * 2);
            asm volatile("st.shared.v2.u32 [%0], {%1, %2};" :: "r"(xh), "r"(h01), "r"(h23));
            asm volatile("st.shared.v2.u32 [%0], {%1, %2};" :: "r"(xl), "r"(l01), "r"(l23));
        }

        if (it < 5) { CPA_WAIT(1); } else { CPA_WAIT(0); }
        __syncthreads();

        if (it < 4) {
            int s = it + 2, ss = s % 3;
#pragma unroll
            for (int j = 0; j < 3; j++) {
                int idx = tid + j * 256;
                int row = idx >> 2;
                int c8  = (idx & 3) << 3;
                cpa16(sb + (uint32_t)((OFF_W(ss) + row * AST + c8) * 2),
                      WhB + (size_t)row * 192 + s * 32 + c8);
            }
            CPA_COMMIT();
        }
        if (it < 5) {
            xv0 = *reinterpret_cast<const float4*>(
                Xb + (size_t)((it + 1) * 32 + xrow) * HWSZ + xc4);
            xv1 = *reinterpret_cast<const float4*>(
                Xb + (size_t)((it + 1) * 32 + xrow + 16) * HWSZ + xc4);
        }

        uint32_t ah[2][3][4], bh[2][2][4], bl[2][2][4];
#pragma unroll
        for (int kh = 0; kh < 2; kh++) {
#pragma unroll
            for (int mi = 0; mi < 3; mi++) {
                int r = wm * 48 + mi * 16 + arow;
                uint32_t addr = sb + (uint32_t)((OFF_W(ws) + r * AST + kh * 16 + acol) * 2);
                asm volatile("ldmatrix.sync.aligned.m8n8.x4.shared.b16 {%0,%1,%2,%3}, [%4];"
                    : "=r"(ah[kh][mi][0]), "=r"(ah[kh][mi][1]),
                      "=r"(ah[kh][mi][2]), "=r"(ah[kh][mi][3]) : "r"(addr));
            }
#pragma unroll
            for (int blk = 0; blk < 2; blk++) {
                int col = wn * 32 + blk * 16 + bcoff;
                int krow = kh * 16 + brow;
                uint32_t addr_h = sb + (uint32_t)((OFF_XH(xs) + krow * BST + col) * 2);
                uint32_t addr_l = sb + (uint32_t)((OFF_XL(xs) + krow * BST + col) * 2);
                asm volatile("ldmatrix.sync.aligned.m8n8.x4.trans.shared.b16 {%0,%1,%2,%3}, [%4];"
                    : "=r"(bh[kh][blk][0]), "=r"(bh[kh][blk][1]),
                      "=r"(bh[kh][blk][2]), "=r"(bh[kh][blk][3]) : "r"(addr_h));
                asm volatile("ldmatrix.sync.aligned.m8n8.x4.trans.shared.b16 {%0,%1,%2,%3}, [%4];"
                    : "=r"(bl[kh][blk][0]), "=r"(bl[kh][blk][1]),
                      "=r"(bl[kh][blk][2]), "=r"(bl[kh][blk][3]) : "r"(addr_l));
            }
        }

#define MMA(C, A, B0, B1) \
    asm volatile("mma.sync.aligned.m16n8k16.row.col.f32.f16.f16.f32 " \
        "{%0,%1,%2,%3}, {%4,%5,%6,%7}, {%8,%9}, {%0,%1,%2,%3};" \
        : "+f"((C)[0]), "+f"((C)[1]), "+f"((C)[2]), "+f"((C)[3]) \
        : "r"((A)[0]), "r"((A)[1]), "r"((A)[2]), "r"((A)[3]), "r"(B0), "r"(B1))

#pragma unroll
        for (int kh = 0; kh < 2; kh++)
#pragma unroll
            for (int mi = 0; mi < 3; mi++)
#pragma unroll
                for (int ni = 0; ni < 4; ni++) {
                    int blk = ni >> 1, hf = (ni & 1) << 1;
                    MMA(acc[mi][ni], ah[kh][mi], bh[kh][blk][hf], bh[kh][blk][hf + 1]);
                    MMA(acc[mi][ni], ah[kh][mi], bl[kh][blk][hf], bl[kh][blk][hf + 1]);
                }
        __syncthreads();
    }

    float* Yb = Y + (size_t)b * ystride_b + (size_t)nt * 192 * HWSZ + p0;
#pragma unroll
    for (int mi = 0; mi < 3; mi++) {
        int r0 = wm * 48 + mi * 16 + (lid >> 2);
#pragma unroll
        for (int ni = 0; ni < 4; ni++) {
            int px = wn * 32 + ni * 8 + (lid & 3) * 2;
            *reinterpret_cast<float2*>(Yb + (size_t)r0 * HWSZ + px) =
                make_float2(acc[mi][ni][0], acc[mi][ni][1]);
            *reinterpret_cast<float2*>(Yb + (size_t)(r0 + 8) * HWSZ + px) =
                make_float2(acc[mi][ni][2], acc[mi][ni][3]);
        }
    }
}

// ================= 1-pass HMMA GEMM, fp16 X (for out = M @ v) =================
#define OFF_X1(s) (23040 + (s) * 2304)
#define GEMM_SMEM_H ((23040 + 2 * 2304) * 2)   // 55296 B

__global__ __launch_bounds__(256, 2) void hmma_gemm_h_kernel(
    const __half* __restrict__ X, long long xstride_b,
    const __half* __restrict__ Wh, long long wstride_b,
    float* __restrict__ Y, long long ystride_b)
{
    extern __shared__ __half sms[];
    const uint32_t sb = smem_u32(sms);

    const int tid = threadIdx.x;
    const int lid = tid & 31;
    const int wid = tid >> 5;
    const int wm  = wid >> 1;
    const int wn  = wid & 1;
    const int p0  = blockIdx.x * 64;
    const int b   = blockIdx.z;

    const __half* Xb = X + (size_t)b * xstride_b + p0;
    const __half* WhB = Wh + (size_t)b * wstride_b;

    float acc[3][4][4];
#pragma unroll
    for (int i = 0; i < 3; i++)
#pragma unroll
        for (int j = 0; j < 4; j++)
#pragma unroll
            for (int r = 0; r < 4; r++) acc[i][j][r] = 0.f;

    // X tile = 32 rows x 64 halfs; each thread owns one 8-half (16B) slice
    const int xrow = tid >> 3, xc8 = (tid & 7) << 3;
    const int arow = (lid & 7) + ((lid >> 3) & 1) * 8;
    const int acol = (lid >> 4) * 8;
    const int brow = arow;
    const int bcoff = ((lid >> 4) & 1) * 8;

#pragma unroll
    for (int s = 0; s < 2; s++) {
#pragma unroll
        for (int j = 0; j < 3; j++) {
            int idx = tid + j * 256;
            int row = idx >> 2;
            int c8  = (idx & 3) << 3;
            cpa16(sb + (uint32_t)((OFF_W(s) + row * AST + c8) * 2),
                  WhB + (size_t)row * 192 + s * 32 + c8);
        }
        CPA_COMMIT();
    }
    uint4 xv = *reinterpret_cast<const uint4*>(Xb + (size_t)xrow * HWSZ + xc8);

#pragma unroll 1
    for (int it = 0; it < 6; it++) {
        const int ws = it % 3;
        const int xs = it & 1;

        {
            uint32_t xa = sb + (uint32_t)((OFF_X1(xs) + xrow * BST + xc8) * 2);
            asm volatile("st.shared.v4.u32 [%0], {%1, %2, %3, %4};"
                :: "r"(xa), "r"(xv.x), "r"(xv.y), "r"(xv.z), "r"(xv.w));
        }

        if (it < 5) { CPA_WAIT(1); } else { CPA_WAIT(0); }
        __syncthreads();

        if (it < 4) {
            int s = it + 2, ss = s % 3;
#pragma unroll
            for (int j = 0; j < 3; j++) {
                int idx = tid + j * 256;
                int row = idx >> 2;
                int c8  = (idx & 3) << 3;
                cpa16(sb + (uint32_t)((OFF_W(ss) + row * AST + c8) * 2),
                      WhB + (size_t)row * 192 + s * 32 + c8);
            }
            CPA_COMMIT();
        }
        if (it < 5)
            xv = *reinterpret_cast<const uint4*>(
                Xb + (size_t)((it + 1) * 32 + xrow) * HWSZ + xc8);

        uint32_t ah[2][3][4], bh[2][2][4];
#pragma unroll
        for (int kh = 0; kh < 2; kh++) {
#pragma unroll
            for (int mi = 0; mi < 3; mi++) {
                int r = wm * 48 + mi * 16 + arow;
                uint32_t addr = sb + (uint32_t)((OFF_W(ws) + r * AST + kh * 16 + acol) * 2);
                asm volatile("ldmatrix.sync.aligned.m8n8.x4.shared.b16 {%0,%1,%2,%3}, [%4];"
                    : "=r"(ah[kh][mi][0]), "=r"(ah[kh][mi][1]),
                      "=r"(ah[kh][mi][2]), "=r"(ah[kh][mi][3]) : "r"(addr));
            }
#pragma unroll
            for (int blk = 0; blk < 2; blk++) {
                int col = wn * 32 + blk * 16 + bcoff;
                int krow = kh * 16 + brow;
                uint32_t addr = sb + (uint32_t)((OFF_X1(xs) + krow * BST + col) * 2);
                asm volatile("ldmatrix.sync.aligned.m8n8.x4.trans.shared.b16 {%0,%1,%2,%3}, [%4];"
                    : "=r"(bh[kh][blk][0]), "=r"(bh[kh][blk][1]),
                      "=r"(bh[kh][blk][2]), "=r"(bh[kh][blk][3]) : "r"(addr));
            }
        }

#pragma unroll
        for (int kh = 0; kh < 2; kh++)
#pragma unroll
            for (int mi = 0; mi < 3; mi++)
#pragma unroll
                for (int ni = 0; ni < 4; ni++) {
                    int blk = ni >> 1, hf = (ni & 1) << 1;
                    MMA(acc[mi][ni], ah[kh][mi], bh[kh][blk][hf], bh[kh][blk][hf + 1]);
                }
        __syncthreads();
    }

    float* Yb = Y + (size_t)b * ystride_b + p0;
#pragma unroll
    for (int mi = 0; mi < 3; mi++) {
        int r0 = wm * 48 + mi * 16 + (lid >> 2);
#pragma unroll
        for (int ni = 0; ni < 4; ni++) {
            int px = wn * 32 + ni * 8 + (lid & 3) * 2;
            *reinterpret_cast<float2*>(Yb + (size_t)r0 * HWSZ + px) =
                make_float2(acc[mi][ni][0], acc[mi][ni][1]);
            *reinterpret_cast<float2*>(Yb + (size_t)(r0 + 8) * HWSZ + px) =
                make_float2(acc[mi][ni][2], acc[mi][ni][3]);
        }
    }
}

// ---------------- dwconv3x3 + Gram + norms + v (4-ch halo, 4 CTAs/SM) ----------------
__device__ __forceinline__ void load_halo4v(float* halo, const float* __restrict__ src,
                                            int chBase, int ty0, int tx0, int tid) {
    for (int i = tid; i < 4 * 324; i += 256) {
        int ch  = i / 324;
        int rem = i - ch * 324;
        int r   = rem / 18;
        int cc  = rem - r * 18;
        int gy = ty0 - 1 + r, gx = tx0 - 1 + cc;
        float vv = 0.f;
        if ((unsigned)gy < 256u && (unsigned)gx < 256u)
            vv = src[(size_t)(chBase + ch) * HWSZ + gy * 256 + gx];
        halo[ch * 360 + r * 20 + cc] = vv;
    }
}

__device__ __forceinline__ float4 dw_quad(const float* hb, const float* wr) {
    float r4[4][4];
#pragma unroll
    for (int r = 0; r < 4; r++) {
        float2 a  = *reinterpret_cast<const float2*>(hb + r * 20);
        float2 b2 = *reinterpret_cast<const float2*>(hb + r * 20 + 2);
        r4[r][0] = a.x; r4[r][1] = a.y; r4[r][2] = b2.x; r4[r][3] = b2.y;
    }
    float ox = 0.f, oy = 0.f, oz = 0.f, ow = 0.f;
#pragma unroll
    for (int i2 = 0; i2 < 3; i2++)
#pragma unroll
        for (int j2 = 0; j2 < 3; j2++) {
            float wv = wr[i2 * 3 + j2];
            ox += r4[i2][j2]     * wv;
            oy += r4[i2][j2 + 1] * wv;
            oz += r4[i2 + 1][j2] * wv;
            ow += r4[i2 + 1][j2 + 1] * wv;
        }
    return make_float4(ox, oy, oz, ow);
}

// smem: halo[4*360] + qs[24*QP2] + ks[24*QP2] = 55680 B -> 4 CTAs/SM
__global__ __launch_bounds__(256, 4) void dw_reduce_kernel(
    const float* __restrict__ pre, const float* __restrict__ wq_dw,
    const float* __restrict__ wkv_dw,
    __half* __restrict__ vout, float* __restrict__ ssq, float* __restrict__ ssk,
    float* __restrict__ gram)
{
    extern __shared__ float sm[];
    float* halo = sm;                  // 1440 floats
    float* qs   = sm + 1440;
    float* ks   = qs + 24 * QP2;

    const int tid = threadIdx.x;
    const int b   = blockIdx.z >> 3;
    const int h   = blockIdx.z & 7;
    const int cb  = h * CH;
    const int tx0 = blockIdx.x * 16;
    const int ty0 = blockIdx.y * 16;

    const int cs = tid >> 6;           // channel slot 0..3
    const int qd = tid & 63;
    const int qy = qd >> 3, qx = qd & 7;
    const int hoff = (2 * qy) * 20 + 2 * qx;

    const float* srcq  = pre + (size_t)b * 3 * CDIM * HWSZ;
    const float* srckv = srcq + (size_t)CDIM * HWSZ;

    // ---- q channels -> qs ----
#pragma unroll 1
    for (int g = 0; g < 6; g++) {
        load_halo4v(halo, srcq, cb + g * 4, ty0, tx0, tid);
        __syncthreads();
        int c = g * 4 + cs;
        const float* w = wq_dw + (size_t)(cb + c) * 9;
        float wr[9];
#pragma unroll
        for (int j = 0; j < 9; j++) wr[j] = __ldg(w + j);
        float4 o = dw_quad(halo + cs * 360 + hoff, wr);
        *reinterpret_cast<float4*>(qs + c * QP2 + qd * 4) = o;
        __syncthreads();
    }
    // ---- k channels -> ks ----
#pragma unroll 1
    for (int g = 0; g < 6; g++) {
        load_halo4v(halo, srckv, cb + g * 4, ty0, tx0, tid);
        __syncthreads();
        int c = g * 4 + cs;
        const float* w = wkv_dw + (size_t)(cb + c) * 9;
        float wr[9];
#pragma unroll
        for (int j = 0; j < 9; j++) wr[j] = __ldg(w + j);
        float4 o = dw_quad(halo + cs * 360 + hoff, wr);
        *reinterpret_cast<float4*>(ks + c * QP2 + qd * 4) = o;
        __syncthreads();
    }

    // ---- sum of squares ----
    if (tid < 192) {
        int c = tid >> 3, s = tid & 7;
        float sq = 0.f, sk = 0.f;
#pragma unroll
        for (int i = 0; i < 8; i++) {
            int j = s + (i << 3);
            float4 a = *reinterpret_cast<const float4*>(qs + c * QP2 + 4 * j);
            sq += a.x * a.x + a.y * a.y + a.z * a.z + a.w * a.w;
            float4 kk = *reinterpret_cast<const float4*>(ks + c * QP2 + 4 * j);
            sk += kk.x * kk.x + kk.y * kk.y + kk.z * kk.z + kk.w * kk.w;
        }
#pragma unroll
        for (int off = 1; off < 8; off <<= 1) {
            sq += __shfl_xor_sync(0xffffffffu, sq, off);
            sk += __shfl_xor_sync(0xffffffffu, sk, off);
        }
        if (s == 0) {
            atomicAdd(&ssq[b * CDIM + cb + c], sq);
            atomicAdd(&ssk[b * CDIM + cb + c], sk);
        }
    }

    // ---- Gram ----
#pragma unroll 1
    for (int t = tid; t < 288; t += 256) {
        int e = t >> 3, s = t & 7;
        int c0 = (e / 6) * 4, d0 = (e % 6) * 4;
        float acc[16];
#pragma unroll
        for (int j = 0; j < 16; j++) acc[j] = 0.f;
#pragma unroll 2
        for (int i = 0; i < 8; i++) {
            int j = s + (i << 3);
            float4 qv[4], kv[4];
#pragma unroll
            for (int r = 0; r < 4; r++) {
                qv[r] = *reinterpret_cast<const float4*>(qs + (c0 + r) * QP2 + 4 * j);
                kv[r] = *reinterpret_cast<const float4*>(ks + (d0 + r) * QP2 + 4 * j);
            }
#pragma unroll
            for (int a = 0; a < 4; a++)
#pragma unroll
                for (int d = 0; d < 4; d++)
                    acc[a * 4 + d] += qv[a].x * kv[d].x + qv[a].y * kv[d].y
                                    + qv[a].z * kv[d].z + qv[a].w * kv[d].w;
        }
#pragma unroll
        for (int off = 1; off < 8; off <<= 1)
#pragma unroll
            for (int j = 0; j < 16; j++)
                acc[j] += __shfl_xor_sync(0xffffffffu, acc[j], off);
        if (s == 0) {
            float* gb = gram + (((size_t)b * NHEADS + h) * CH + c0) * CH + d0;
#pragma unroll
            for (int jq = 0; jq < 4; jq++)
#pragma unroll
                for (int jk = 0; jk < 4; jk++)
                    atomicAdd(&gb[jq * CH + jk], acc[jq * 4 + jk]);
        }
    }

    // ---- v channels -> global (fp16 half2 rows) ----
#pragma unroll 1
    for (int g = 0; g < 6; g++) {
        load_halo4v(halo, srckv, CDIM + cb + g * 4, ty0, tx0, tid);
        __syncthreads();
        int c = g * 4 + cs;
        const float* w = wkv_dw + (size_t)(CDIM + cb + c) * 9;
        float wr[9];
#pragma unroll
        for (int j = 0; j < 9; j++) wr[j] = __ldg(w + j);
        float4 o = dw_quad(halo + cs * 360 + hoff, wr);
        __half* dst = vout + ((size_t)b * CDIM + cb + c) * HWSZ
                    + (ty0 + 2 * qy) * 256 + (tx0 + 2 * qx);
        uint32_t p0w = (uint32_t)__half_as_ushort(__float2half_rn(o.x))
                     | ((uint32_t)__half_as_ushort(__float2half_rn(o.y)) << 16);
        uint32_t p1w = (uint32_t)__half_as_ushort(__float2half_rn(o.z))
                     | ((uint32_t)__half_as_ushort(__float2half_rn(o.w)) << 16);
        *reinterpret_cast<uint32_t*>(dst)       = p0w;
        *reinterpret_cast<uint32_t*>(dst + 256) = p1w;
        __syncthreads();
    }
}

// ---------------- softmax + M = Wproj * blockdiag(attn) ----------------
__global__ __launch_bounds__(256) void attn_proj_kernel(
    const float* __restrict__ gram, const float* __restrict__ ssq,
    const float* __restrict__ ssk,  const float* __restrict__ temp,
    const float* __restrict__ wproj, float* __restrict__ Mout)
{
    __shared__ float at[192][25];
    __shared__ float nk_s[192];
    const int b = blockIdx.x, tid = threadIdx.x;

    if (tid < 192) nk_s[tid] = fmaxf(sqrtf(ssk[b * CDIM + tid]), 1e-12f);
    __syncthreads();

    if (tid < 192) {
        int h = tid / 24, c = tid % 24;
        float nq = fmaxf(sqrtf(ssq[b * CDIM + tid]), 1e-12f);
        float tv = temp[h];
        const float* gr = gram + (((size_t)b * NHEADS + h) * CH + c) * CH;
        float vals[24];
        float mx = -1e30f;
#pragma unroll
        for (int d = 0; d < 24; d++) {
            float v = gr[d] / (nq * nk_s[h * 24 + d]) * tv;
            vals[d] = v;
            mx = fmaxf(mx, v);
        }
        float s = 0.f;
#pragma unroll
        for (int d = 0; d < 24; d++) { vals[d] = expf(vals[d] - mx); s += vals[d]; }
        float inv = 1.f / s;
#pragma unroll
        for (int d = 0; d < 24; d++) at[tid][d] = vals[d] * inv;
    }
    __syncthreads();

    for (int idx = tid; idx < 192 * 192; idx += 256) {
        int o = idx / 192, dg = idx % 192;
        int h = dg / 24, d = dg % 24;
        float s = 0.f;
#pragma unroll
        for (int c = 0; c < 24; c++)
            s += wproj[o * 192 + h * 24 + c] * at[h * 24 + c][d];
        Mout[(size_t)b * CDIM * CDIM + idx] = s;
    }
}

// ---------------- launch ----------------
extern "C" void kernel_launch(void* const* d_in, const int* in_sizes, int n_in,
                              void* d_out, int out_size) {
    const float* x      = (const float*)d_in[0];
    const float* x_ref  = (const float*)d_in[1];
    const float* wq     = (const float*)d_in[2];
    const float* wq_dw  = (const float*)d_in[3];
    const float* wkv    = (const float*)d_in[4];
    const float* wkv_dw = (const float*)d_in[5];
    const float* wproj  = (const float*)d_in[6];
    const float* temp   = (const float*)d_in[7];
    float* out = (float*)d_out;

    float *pre, *gram, *ssq, *ssk, *Mm;
    __half *vh, *wqkv, *whm;
    cudaGetSymbolAddress((void**)&pre,  g_pre);
    cudaGetSymbolAddress((void**)&vh,   g_vh);
    cudaGetSymbolAddress((void**)&gram, g_gram);
    cudaGetSymbolAddress((void**)&ssq,  g_ssq);
    cudaGetSymbolAddress((void**)&ssk,  g_ssk);
    cudaGetSymbolAddress((void**)&Mm,   g_M);
    cudaGetSymbolAddress((void**)&wqkv, g_wqkv);
    cudaGetSymbolAddress((void**)&whm,  g_whm);

    const int smem2 = (1440 + 2 * 24 * QP2) * (int)sizeof(float);   // 55680 B
    cudaFuncSetAttribute(dw_reduce_kernel,
                         cudaFuncAttributeMaxDynamicSharedMemorySize, smem2);
    cudaFuncSetAttribute(hmma_gemm_kernel,
                         cudaFuncAttributeMaxDynamicSharedMemorySize, GEMM_SMEM);
    cudaFuncSetAttribute(hmma_gemm_h_kernel,
                         cudaFuncAttributeMaxDynamicSharedMemorySize, GEMM_SMEM_H);

    zero_stats_kernel<<<36, 256>>>(gram, ssq, ssk);

    // W -> fp16: wq into slot 0, wkv into slots 1,2
    w2f16_kernel<<<dim3(144, 1, 1), 256>>>(wq,  0LL, CDIM * CDIM, wqkv, 0LL);
    w2f16_kernel<<<dim3(288, 1, 1), 256>>>(wkv, 0LL, 2 * CDIM * CDIM,
                                           wqkv + CDIM * CDIM, 0LL);

    // pre (q | kv), contiguous scratch
    hmma_gemm_kernel<<<dim3(1024, 1, BSZ), 256, GEMM_SMEM>>>(
        x, (long long)CDIM * HWSZ, wqkv, 0LL,
        pre, (long long)3 * CDIM * HWSZ);
    hmma_gemm_kernel<<<dim3(1024, 2, BSZ), 256, GEMM_SMEM>>>(
        x_ref, (long long)CDIM * HWSZ, wqkv + CDIM * CDIM, 0LL,
        pre + (size_t)CDIM * HWSZ, (long long)3 * CDIM * HWSZ);

    dw_reduce_kernel<<<dim3(16, 16, BSZ * NHEADS), 256, smem2>>>(
        pre, wq_dw, wkv_dw, vh, ssq, ssk, gram);

    attn_proj_kernel<<<BSZ, 256>>>(gram, ssq, ssk, temp, wproj, Mm);

    // M -> fp16, then out = M_b @ v  (1-pass fp16 GEMM)
    w2f16_kernel<<<dim3(144, 1, BSZ), 256>>>(Mm, (long long)CDIM * CDIM,
                                             CDIM * CDIM, whm,
                                             (long long)CDIM * CDIM);
    hmma_gemm_h_kernel<<<dim3(1024, 1, BSZ), 256, GEMM_SMEM_H>>>(
        vh, (long long)CDIM * HWSZ, whm, (long long)CDIM * CDIM,
        out, (long long)CDIM * HWSZ);
}

// round 14
// speedup vs baseline: 1.1740x; 1.1740x over previous
#include <cuda_runtime.h>
#include <cuda_fp16.h>
#include <cstdint>

#define HWSZ  65536
#define CDIM  192
#define NHEADS 8
#define CH    24
#define BSZ   2
#define QP2   260

// ---------------- scratch (no cudaMalloc allowed) ----------------
__device__ float  g_pre [(size_t)BSZ * 3 * CDIM * HWSZ];   // q (nt0) + kv (nt1,2)
__device__ __half g_vh  [(size_t)BSZ * CDIM     * HWSZ];   // v in fp16
__device__ float  g_gram[BSZ * NHEADS * CH * CH];
__device__ float  g_ssq [BSZ * CDIM];
__device__ float  g_ssk [BSZ * CDIM];
__device__ float  g_M   [BSZ * CDIM * CDIM];

// fp16 weights: slot 0 = wq, slots 1,2 = wkv   (row-major [rows][192])
__device__ __half g_wqkv[3 * CDIM * CDIM];
__device__ __half g_whm [BSZ * CDIM * CDIM];

__device__ __forceinline__ uint32_t smem_u32(const void* p) {
    uint32_t a;
    asm("{ .reg .u64 t; cvta.to.shared.u64 t, %1; cvt.u32.u64 %0, t; }" : "=r"(a) : "l"(p));
    return a;
}
__device__ __forceinline__ void cpa16(uint32_t dst, const void* src) {
    asm volatile("cp.async.cg.shared.global [%0], [%1], 16;" :: "r"(dst), "l"(src));
}
#define CPA_COMMIT() asm volatile("cp.async.commit_group;" ::: "memory")
#define CPA_WAIT(n)  asm volatile("cp.async.wait_group %0;" :: "n"(n) : "memory")

// ---------------- zero accumulators ----------------
__global__ void zero_stats_kernel(float* gram, float* ssq, float* ssk) {
    int i = blockIdx.x * 256 + threadIdx.x;
    if (i < BSZ * NHEADS * CH * CH) gram[i] = 0.f;
    if (i < BSZ * CDIM) { ssq[i] = 0.f; ssk[i] = 0.f; }
}

// ---------------- prep: fp32 W -> fp16 ----------------
__global__ void w2f16_kernel(const float* __restrict__ W, long long wstride_b,
                             int total, __half* __restrict__ out, long long ostride_b) {
    int b = blockIdx.z;
    int i = blockIdx.x * 256 + threadIdx.x;
    if (i >= total) return;
    out[(size_t)b * ostride_b + i] = __float2half_rn(W[(size_t)b * wstride_b + i]);
}

// ================= pipelined HMMA fp16 2-pass GEMM, BK=32 (fp32 X) =================
#define AST 40
#define BST 72
#define OFF_W(s)  ((s) * 7680)
#define OFF_XH(s) (23040 + (s) * 4608)
#define OFF_XL(s) (23040 + (s) * 4608 + 2304)
#define GEMM_SMEM (32256 * 2)

__global__ __launch_bounds__(256, 2) void hmma_gemm_kernel(
    const float* __restrict__ X, long long xstride_b,
    const __half* __restrict__ Wh, long long wstride_b,
    float* __restrict__ Y, long long ystride_b)
{
    extern __shared__ __half sms[];
    const uint32_t sb = smem_u32(sms);

    const int tid = threadIdx.x;
    const int lid = tid & 31;
    const int wid = tid >> 5;
    const int wm  = wid >> 1;
    const int wn  = wid & 1;
    const int p0  = blockIdx.x * 64;
    const int nt  = blockIdx.y;
    const int b   = blockIdx.z;

    const float* Xb = X + (size_t)b * xstride_b + p0;
    const __half* WhB = Wh + (size_t)b * wstride_b + (size_t)nt * 192 * 192;

    float acc[3][4][4];
#pragma unroll
    for (int i = 0; i < 3; i++)
#pragma unroll
        for (int j = 0; j < 4; j++)
#pragma unroll
            for (int r = 0; r < 4; r++) acc[i][j][r] = 0.f;

    const int xrow = tid >> 4, xc4 = (tid & 15) << 2;
    const int arow = (lid & 7) + ((lid >> 3) & 1) * 8;
    const int acol = (lid >> 4) * 8;
    const int brow = arow;
    const int bcoff = ((lid >> 4) & 1) * 8;

#pragma unroll
    for (int s = 0; s < 2; s++) {
#pragma unroll
        for (int j = 0; j < 3; j++) {
            int idx = tid + j * 256;
            int row = idx >> 2;
            int c8  = (idx & 3) << 3;
            cpa16(sb + (uint32_t)((OFF_W(s) + row * AST + c8) * 2),
                  WhB + (size_t)row * 192 + s * 32 + c8);
        }
        CPA_COMMIT();
    }
    float4 xv0 = *reinterpret_cast<const float4*>(Xb + (size_t)xrow * HWSZ + xc4);
    float4 xv1 = *reinterpret_cast<const float4*>(Xb + (size_t)(xrow + 16) * HWSZ + xc4);

#pragma unroll 1
    for (int it = 0; it < 6; it++) {
        const int ws = it % 3;
        const int xs = it & 1;

#pragma unroll
        for (int hlf = 0; hlf < 2; hlf++) {
            float4 v = hlf ? xv1 : xv0;
            int row = xrow + hlf * 16;
            __half hx = __float2half_rn(v.x), hy = __float2half_rn(v.y);
            __half hz = __float2half_rn(v.z), hw = __float2half_rn(v.w);
            uint32_t h01 = (uint32_t)__half_as_ushort(hx)
                         | ((uint32_t)__half_as_ushort(hy) << 16);
            uint32_t h23 = (uint32_t)__half_as_ushort(hz)
                         | ((uint32_t)__half_as_ushort(hw) << 16);
            __half lx = __float2half_rn(v.x - __half2float(hx));
            __half ly = __float2half_rn(v.y - __half2float(hy));
            __half lz = __float2half_rn(v.z - __half2float(hz));
            __half lw = __float2half_rn(v.w - __half2float(hw));
            uint32_t l01 = (uint32_t)__half_as_ushort(lx)
                         | ((uint32_t)__half_as_ushort(ly) << 16);
            uint32_t l23 = (uint32_t)__half_as_ushort(lz)
                         | ((uint32_t)__half_as_ushort(lw) << 16);
            uint32_t xh = sb + (uint32_t)((OFF_XH(xs) + row * BST + xc4) * 2);
            uint32_t xl = sb + (uint32_t)((OFF_XL(xs) + row * BST + xc4) * 2);
            asm volatile("st.shared.v2.u32 [%0], {%1, %2};" :: "r"(xh), "r"(h01), "r"(h23));
            asm volatile("st.shared.v2.u32 [%0], {%1, %2};" :: "r"(xl), "r"(l01), "r"(l23));
        }

        if (it < 5) { CPA_WAIT(1); } else { CPA_WAIT(0); }
        __syncthreads();

        if (it < 4) {
            int s = it + 2, ss = s % 3;
#pragma unroll
            for (int j = 0; j < 3; j++) {
                int idx = tid + j * 256;
                int row = idx >> 2;
                int c8  = (idx & 3) << 3;
                cpa16(sb + (uint32_t)((OFF_W(ss) + row * AST + c8) * 2),
                      WhB + (size_t)row * 192 + s * 32 + c8);
            }
            CPA_COMMIT();
        }
        if (it < 5) {
            xv0 = *reinterpret_cast<const float4*>(
                Xb + (size_t)((it + 1) * 32 + xrow) * HWSZ + xc4);
            xv1 = *reinterpret_cast<const float4*>(
                Xb + (size_t)((it + 1) * 32 + xrow + 16) * HWSZ + xc4);
        }

        uint32_t ah[2][3][4], bh[2][2][4], bl[2][2][4];
#pragma unroll
        for (int kh = 0; kh < 2; kh++) {
#pragma unroll
            for (int mi = 0; mi < 3; mi++) {
                int r = wm * 48 + mi * 16 + arow;
                uint32_t addr = sb + (uint32_t)((OFF_W(ws) + r * AST + kh * 16 + acol) * 2);
                asm volatile("ldmatrix.sync.aligned.m8n8.x4.shared.b16 {%0,%1,%2,%3}, [%4];"
                    : "=r"(ah[kh][mi][0]), "=r"(ah[kh][mi][1]),
                      "=r"(ah[kh][mi][2]), "=r"(ah[kh][mi][3]) : "r"(addr));
            }
#pragma unroll
            for (int blk = 0; blk < 2; blk++) {
                int col = wn * 32 + blk * 16 + bcoff;
                int krow = kh * 16 + brow;
                uint32_t addr_h = sb + (uint32_t)((OFF_XH(xs) + krow * BST + col) * 2);
                uint32_t addr_l = sb + (uint32_t)((OFF_XL(xs) + krow * BST + col) * 2);
                asm volatile("ldmatrix.sync.aligned.m8n8.x4.trans.shared.b16 {%0,%1,%2,%3}, [%4];"
                    : "=r"(bh[kh][blk][0]), "=r"(bh[kh][blk][1]),
                      "=r"(bh[kh][blk][2]), "=r"(bh[kh][blk][3]) : "r"(addr_h));
                asm volatile("ldmatrix.sync.aligned.m8n8.x4.trans.shared.b16 {%0,%1,%2,%3}, [%4];"
                    : "=r"(bl[kh][blk][0]), "=r"(bl[kh][blk][1]),
                      "=r"(bl[kh][blk][2]), "=r"(bl[kh][blk][3]) : "r"(addr_l));
            }
        }

#define MMA(C, A, B0, B1) \
    asm volatile("mma.sync.aligned.m16n8k16.row.col.f32.f16.f16.f32 " \
        "{%0,%1,%2,%3}, {%4,%5,%6,%7}, {%8,%9}, {%0,%1,%2,%3};" \
        : "+f"((C)[0]), "+f"((C)[1]), "+f"((C)[2]), "+f"((C)[3]) \
        : "r"((A)[0]), "r"((A)[1]), "r"((A)[2]), "r"((A)[3]), "r"(B0), "r"(B1))

#pragma unroll
        for (int kh = 0; kh < 2; kh++)
#pragma unroll
            for (int mi = 0; mi < 3; mi++)
#pragma unroll
                for (int ni = 0; ni < 4; ni++) {
                    int blk = ni >> 1, hf = (ni & 1) << 1;
                    MMA(acc[mi][ni], ah[kh][mi], bh[kh][blk][hf], bh[kh][blk][hf + 1]);
                    MMA(acc[mi][ni], ah[kh][mi], bl[kh][blk][hf], bl[kh][blk][hf + 1]);
                }
        __syncthreads();
    }

    float* Yb = Y + (size_t)b * ystride_b + (size_t)nt * 192 * HWSZ + p0;
#pragma unroll
    for (int mi = 0; mi < 3; mi++) {
        int r0 = wm * 48 + mi * 16 + (lid >> 2);
#pragma unroll
        for (int ni = 0; ni < 4; ni++) {
            int px = wn * 32 + ni * 8 + (lid & 3) * 2;
            *reinterpret_cast<float2*>(Yb + (size_t)r0 * HWSZ + px) =
                make_float2(acc[mi][ni][0], acc[mi][ni][1]);
            *reinterpret_cast<float2*>(Yb + (size_t)(r0 + 8) * HWSZ + px) =
                make_float2(acc[mi][ni][2], acc[mi][ni][3]);
        }
    }
}

// ================= 1-pass HMMA GEMM, fp16 X (for out = M @ v) =================
#define OFF_X1(s) (23040 + (s) * 2304)
#define GEMM_SMEM_H ((23040 + 2 * 2304) * 2)   // 55296 B

__global__ __launch_bounds__(256, 2) void hmma_gemm_h_kernel(
    const __half* __restrict__ X, long long xstride_b,
    const __half* __restrict__ Wh, long long wstride_b,
    float* __restrict__ Y, long long ystride_b)
{
    extern __shared__ __half sms[];
    const uint32_t sb = smem_u32(sms);

    const int tid = threadIdx.x;
    const int lid = tid & 31;
    const int wid = tid >> 5;
    const int wm  = wid >> 1;
    const int wn  = wid & 1;
    const int p0  = blockIdx.x * 64;
    const int b   = blockIdx.z;

    const __half* Xb = X + (size_t)b * xstride_b + p0;
    const __half* WhB = Wh + (size_t)b * wstride_b;

    float acc[3][4][4];
#pragma unroll
    for (int i = 0; i < 3; i++)
#pragma unroll
        for (int j = 0; j < 4; j++)
#pragma unroll
            for (int r = 0; r < 4; r++) acc[i][j][r] = 0.f;

    // X tile = 32 rows x 64 halfs; each thread owns one 8-half (16B) slice
    const int xrow = tid >> 3, xc8 = (tid & 7) << 3;
    const int arow = (lid & 7) + ((lid >> 3) & 1) * 8;
    const int acol = (lid >> 4) * 8;
    const int brow = arow;
    const int bcoff = ((lid >> 4) & 1) * 8;

#pragma unroll
    for (int s = 0; s < 2; s++) {
#pragma unroll
        for (int j = 0; j < 3; j++) {
            int idx = tid + j * 256;
            int row = idx >> 2;
            int c8  = (idx & 3) << 3;
            cpa16(sb + (uint32_t)((OFF_W(s) + row * AST + c8) * 2),
                  WhB + (size_t)row * 192 + s * 32 + c8);
        }
        CPA_COMMIT();
    }
    uint4 xv = *reinterpret_cast<const uint4*>(Xb + (size_t)xrow * HWSZ + xc8);

#pragma unroll 1
    for (int it = 0; it < 6; it++) {
        const int ws = it % 3;
        const int xs = it & 1;

        {
            uint32_t xa = sb + (uint32_t)((OFF_X1(xs) + xrow * BST + xc8) * 2);
            asm volatile("st.shared.v4.u32 [%0], {%1, %2, %3, %4};"
                :: "r"(xa), "r"(xv.x), "r"(xv.y), "r"(xv.z), "r"(xv.w));
        }

        if (it < 5) { CPA_WAIT(1); } else { CPA_WAIT(0); }
        __syncthreads();

        if (it < 4) {
            int s = it + 2, ss = s % 3;
#pragma unroll
            for (int j = 0; j < 3; j++) {
                int idx = tid + j * 256;
                int row = idx >> 2;
                int c8  = (idx & 3) << 3;
                cpa16(sb + (uint32_t)((OFF_W(ss) + row * AST + c8) * 2),
                      WhB + (size_t)row * 192 + s * 32 + c8);
            }
            CPA_COMMIT();
        }
        if (it < 5)
            xv = *reinterpret_cast<const uint4*>(
                Xb + (size_t)((it + 1) * 32 + xrow) * HWSZ + xc8);

        uint32_t ah[2][3][4], bh[2][2][4];
#pragma unroll
        for (int kh = 0; kh < 2; kh++) {
#pragma unroll
            for (int mi = 0; mi < 3; mi++) {
                int r = wm * 48 + mi * 16 + arow;
                uint32_t addr = sb + (uint32_t)((OFF_W(ws) + r * AST + kh * 16 + acol) * 2);
                asm volatile("ldmatrix.sync.aligned.m8n8.x4.shared.b16 {%0,%1,%2,%3}, [%4];"
                    : "=r"(ah[kh][mi][0]), "=r"(ah[kh][mi][1]),
                      "=r"(ah[kh][mi][2]), "=r"(ah[kh][mi][3]) : "r"(addr));
            }
#pragma unroll
            for (int blk = 0; blk < 2; blk++) {
                int col = wn * 32 + blk * 16 + bcoff;
                int krow = kh * 16 + brow;
                uint32_t addr = sb + (uint32_t)((OFF_X1(xs) + krow * BST + col) * 2);
                asm volatile("ldmatrix.sync.aligned.m8n8.x4.trans.shared.b16 {%0,%1,%2,%3}, [%4];"
                    : "=r"(bh[kh][blk][0]), "=r"(bh[kh][blk][1]),
                      "=r"(bh[kh][blk][2]), "=r"(bh[kh][blk][3]) : "r"(addr));
            }
        }

#pragma unroll
        for (int kh = 0; kh < 2; kh++)
#pragma unroll
            for (int mi = 0; mi < 3; mi++)
#pragma unroll
                for (int ni = 0; ni < 4; ni++) {
                    int blk = ni >> 1, hf = (ni & 1) << 1;
                    MMA(acc[mi][ni], ah[kh][mi], bh[kh][blk][hf], bh[kh][blk][hf + 1]);
                }
        __syncthreads();
    }

    float* Yb = Y + (size_t)b * ystride_b + p0;
#pragma unroll
    for (int mi = 0; mi < 3; mi++) {
        int r0 = wm * 48 + mi * 16 + (lid >> 2);
#pragma unroll
        for (int ni = 0; ni < 4; ni++) {
            int px = wn * 32 + ni * 8 + (lid & 3) * 2;
            *reinterpret_cast<float2*>(Yb + (size_t)r0 * HWSZ + px) =
                make_float2(acc[mi][ni][0], acc[mi][ni][1]);
            *reinterpret_cast<float2*>(Yb + (size_t)(r0 + 8) * HWSZ + px) =
                make_float2(acc[mi][ni][2], acc[mi][ni][3]);
        }
    }
}

// ---------------- dwconv3x3 + Gram + norms + v (R11 structure, fp16 v out) ----------------
__device__ __forceinline__ void load_halo8v(float* halo, const float* __restrict__ src,
                                            int chBase, int ty0, int tx0, int tid) {
    for (int i = tid; i < 8 * 324; i += 256) {
        int ch  = i / 324;
        int rem = i - ch * 324;
        int r   = rem / 18;
        int cc  = rem - r * 18;
        int gy = ty0 - 1 + r, gx = tx0 - 1 + cc;
        float vv = 0.f;
        if ((unsigned)gy < 256u && (unsigned)gx < 256u)
            vv = src[(size_t)(chBase + ch) * HWSZ + gy * 256 + gx];
        halo[ch * 360 + r * 20 + cc] = vv;
    }
}

__device__ __forceinline__ float4 dw_quad(const float* hb, const float* wr) {
    float r4[4][4];
#pragma unroll
    for (int r = 0; r < 4; r++) {
        float2 a  = *reinterpret_cast<const float2*>(hb + r * 20);
        float2 b2 = *reinterpret_cast<const float2*>(hb + r * 20 + 2);
        r4[r][0] = a.x; r4[r][1] = a.y; r4[r][2] = b2.x; r4[r][3] = b2.y;
    }
    float ox = 0.f, oy = 0.f, oz = 0.f, ow = 0.f;
#pragma unroll
    for (int i2 = 0; i2 < 3; i2++)
#pragma unroll
        for (int j2 = 0; j2 < 3; j2++) {
            float wv = wr[i2 * 3 + j2];
            ox += r4[i2][j2]     * wv;
            oy += r4[i2][j2 + 1] * wv;
            oz += r4[i2 + 1][j2] * wv;
            ow += r4[i2 + 1][j2 + 1] * wv;
        }
    return make_float4(ox, oy, oz, ow);
}

// smem: halo[8*360] + qs[24*QP2] + ks[24*QP2] = 61440 B -> 3 CTAs/SM
__global__ __launch_bounds__(256) void dw_reduce_kernel(
    const float* __restrict__ pre, const float* __restrict__ wq_dw,
    const float* __restrict__ wkv_dw,
    __half* __restrict__ vout, float* __restrict__ ssq, float* __restrict__ ssk,
    float* __restrict__ gram)
{
    extern __shared__ float sm[];
    float* halo = sm;                  // 2880 floats
    float* qs   = sm + 2880;
    float* ks   = qs + 24 * QP2;

    const int tid = threadIdx.x;
    const int b   = blockIdx.z >> 3;
    const int h   = blockIdx.z & 7;
    const int cb  = h * CH;
    const int tx0 = blockIdx.x * 16;
    const int ty0 = blockIdx.y * 16;

    const int cs = tid >> 6;
    const int qd = tid & 63;
    const int qy = qd >> 3, qx = qd & 7;
    const int hoff = (2 * qy) * 20 + 2 * qx;

    const float* srcq  = pre + (size_t)b * 3 * CDIM * HWSZ;
    const float* srckv = srcq + (size_t)CDIM * HWSZ;

    // ---- q channels -> qs ----
#pragma unroll 1
    for (int g = 0; g < 3; g++) {
        load_halo8v(halo, srcq, cb + g * 8, ty0, tx0, tid);
        __syncthreads();
#pragma unroll
        for (int it = 0; it < 2; it++) {
            int cc = cs + it * 4;
            int c  = g * 8 + cc;
            const float* w = wq_dw + (size_t)(cb + c) * 9;
            float wr[9];
#pragma unroll
            for (int j = 0; j < 9; j++) wr[j] = __ldg(w + j);
            float4 o = dw_quad(halo + cc * 360 + hoff, wr);
            *reinterpret_cast<float4*>(qs + c * QP2 + qd * 4) = o;
        }
        __syncthreads();
    }
    // ---- k channels -> ks ----
#pragma unroll 1
    for (int g = 0; g < 3; g++) {
        load_halo8v(halo, srckv, cb + g * 8, ty0, tx0, tid);
        __syncthreads();
#pragma unroll
        for (int it = 0; it < 2; it++) {
            int cc = cs + it * 4;
            int c  = g * 8 + cc;
            const float* w = wkv_dw + (size_t)(cb + c) * 9;
            float wr[9];
#pragma unroll
            for (int j = 0; j < 9; j++) wr[j] = __ldg(w + j);
            float4 o = dw_quad(halo + cc * 360 + hoff, wr);
            *reinterpret_cast<float4*>(ks + c * QP2 + qd * 4) = o;
        }
        __syncthreads();
    }

    // ---- sum of squares ----
    if (tid < 192) {
        int c = tid >> 3, s = tid & 7;
        float sq = 0.f, sk = 0.f;
#pragma unroll
        for (int i = 0; i < 8; i++) {
            int j = s + (i << 3);
            float4 a = *reinterpret_cast<const float4*>(qs + c * QP2 + 4 * j);
            sq += a.x * a.x + a.y * a.y + a.z * a.z + a.w * a.w;
            float4 kk = *reinterpret_cast<const float4*>(ks + c * QP2 + 4 * j);
            sk += kk.x * kk.x + kk.y * kk.y + kk.z * kk.z + kk.w * kk.w;
        }
#pragma unroll
        for (int off = 1; off < 8; off <<= 1) {
            sq += __shfl_xor_sync(0xffffffffu, sq, off);
            sk += __shfl_xor_sync(0xffffffffu, sk, off);
        }
        if (s == 0) {
            atomicAdd(&ssq[b * CDIM + cb + c], sq);
            atomicAdd(&ssk[b * CDIM + cb + c], sk);
        }
    }

    // ---- Gram ----
#pragma unroll 1
    for (int t = tid; t < 288; t += 256) {
        int e = t >> 3, s = t & 7;
        int c0 = (e / 6) * 4, d0 = (e % 6) * 4;
        float acc[16];
#pragma unroll
        for (int j = 0; j < 16; j++) acc[j] = 0.f;
#pragma unroll 2
        for (int i = 0; i < 8; i++) {
            int j = s + (i << 3);
            float4 qv[4], kv[4];
#pragma unroll
            for (int r = 0; r < 4; r++) {
                qv[r] = *reinterpret_cast<const float4*>(qs + (c0 + r) * QP2 + 4 * j);
                kv[r] = *reinterpret_cast<const float4*>(ks + (d0 + r) * QP2 + 4 * j);
            }
#pragma unroll
            for (int a = 0; a < 4; a++)
#pragma unroll
                for (int d = 0; d < 4; d++)
                    acc[a * 4 + d] += qv[a].x * kv[d].x + qv[a].y * kv[d].y
                                    + qv[a].z * kv[d].z + qv[a].w * kv[d].w;
        }
#pragma unroll
        for (int off = 1; off < 8; off <<= 1)
#pragma unroll
            for (int j = 0; j < 16; j++)
                acc[j] += __shfl_xor_sync(0xffffffffu, acc[j], off);
        if (s == 0) {
            float* gb = gram + (((size_t)b * NHEADS + h) * CH + c0) * CH + d0;
#pragma unroll
            for (int jq = 0; jq < 4; jq++)
#pragma unroll
                for (int jk = 0; jk < 4; jk++)
                    atomicAdd(&gb[jq * CH + jk], acc[jq * 4 + jk]);
        }
    }

    // ---- v channels -> global (fp16 half2 rows) ----
#pragma unroll 1
    for (int g = 0; g < 3; g++) {
        load_halo8v(halo, srckv, CDIM + cb + g * 8, ty0, tx0, tid);
        __syncthreads();
#pragma unroll
        for (int it = 0; it < 2; it++) {
            int cc = cs + it * 4;
            int c  = g * 8 + cc;
            const float* w = wkv_dw + (size_t)(CDIM + cb + c) * 9;
            float wr[9];
#pragma unroll
            for (int j = 0; j < 9; j++) wr[j] = __ldg(w + j);
            float4 o = dw_quad(halo + cc * 360 + hoff, wr);
            __half* dst = vout + ((size_t)b * CDIM + cb + c) * HWSZ
                        + (ty0 + 2 * qy) * 256 + (tx0 + 2 * qx);
            uint32_t p0w = (uint32_t)__half_as_ushort(__float2half_rn(o.x))
                         | ((uint32_t)__half_as_ushort(__float2half_rn(o.y)) << 16);
            uint32_t p1w = (uint32_t)__half_as_ushort(__float2half_rn(o.z))
                         | ((uint32_t)__half_as_ushort(__float2half_rn(o.w)) << 16);
            *reinterpret_cast<uint32_t*>(dst)       = p0w;
            *reinterpret_cast<uint32_t*>(dst + 256) = p1w;
        }
        __syncthreads();
    }
}

// ---------------- softmax + M = Wproj * blockdiag(attn) ----------------
__global__ __launch_bounds__(256) void attn_proj_kernel(
    const float* __restrict__ gram, const float* __restrict__ ssq,
    const float* __restrict__ ssk,  const float* __restrict__ temp,
    const float* __restrict__ wproj, float* __restrict__ Mout)
{
    __shared__ float at[192][25];
    __shared__ float nk_s[192];
    const int b = blockIdx.x, tid = threadIdx.x;

    if (tid < 192) nk_s[tid] = fmaxf(sqrtf(ssk[b * CDIM + tid]), 1e-12f);
    __syncthreads();

    if (tid < 192) {
        int h = tid / 24, c = tid % 24;
        float nq = fmaxf(sqrtf(ssq[b * CDIM + tid]), 1e-12f);
        float tv = temp[h];
        const float* gr = gram + (((size_t)b * NHEADS + h) * CH + c) * CH;
        float vals[24];
        float mx = -1e30f;
#pragma unroll
        for (int d = 0; d < 24; d++) {
            float v = gr[d] / (nq * nk_s[h * 24 + d]) * tv;
            vals[d] = v;
            mx = fmaxf(mx, v);
        }
        float s = 0.f;
#pragma unroll
        for (int d = 0; d < 24; d++) { vals[d] = expf(vals[d] - mx); s += vals[d]; }
        float inv = 1.f / s;
#pragma unroll
        for (int d = 0; d < 24; d++) at[tid][d] = vals[d] * inv;
    }
    __syncthreads();

    for (int idx = tid; idx < 192 * 192; idx += 256) {
        int o = idx / 192, dg = idx % 192;
        int h = dg / 24, d = dg % 24;
        float s = 0.f;
#pragma unroll
        for (int c = 0; c < 24; c++)
            s += wproj[o * 192 + h * 24 + c] * at[h * 24 + c][d];
        Mout[(size_t)b * CDIM * CDIM + idx] = s;
    }
}

// ---------------- launch ----------------
extern "C" void kernel_launch(void* const* d_in, const int* in_sizes, int n_in,
                              void* d_out, int out_size) {
    const float* x      = (const float*)d_in[0];
    const float* x_ref  = (const float*)d_in[1];
    const float* wq     = (const float*)d_in[2];
    const float* wq_dw  = (const float*)d_in[3];
    const float* wkv    = (const float*)d_in[4];
    const float* wkv_dw = (const float*)d_in[5];
    const float* wproj  = (const float*)d_in[6];
    const float* temp   = (const float*)d_in[7];
    float* out = (float*)d_out;

    float *pre, *gram, *ssq, *ssk, *Mm;
    __half *vh, *wqkv, *whm;
    cudaGetSymbolAddress((void**)&pre,  g_pre);
    cudaGetSymbolAddress((void**)&vh,   g_vh);
    cudaGetSymbolAddress((void**)&gram, g_gram);
    cudaGetSymbolAddress((void**)&ssq,  g_ssq);
    cudaGetSymbolAddress((void**)&ssk,  g_ssk);
    cudaGetSymbolAddress((void**)&Mm,   g_M);
    cudaGetSymbolAddress((void**)&wqkv, g_wqkv);
    cudaGetSymbolAddress((void**)&whm,  g_whm);

    const int smem2 = (2880 + 2 * 24 * QP2) * (int)sizeof(float);   // 61440 B
    cudaFuncSetAttribute(dw_reduce_kernel,
                         cudaFuncAttributeMaxDynamicSharedMemorySize, smem2);
    cudaFuncSetAttribute(hmma_gemm_kernel,
                         cudaFuncAttributeMaxDynamicSharedMemorySize, GEMM_SMEM);
    cudaFuncSetAttribute(hmma_gemm_h_kernel,
                         cudaFuncAttributeMaxDynamicSharedMemorySize, GEMM_SMEM_H);

    zero_stats_kernel<<<36, 256>>>(gram, ssq, ssk);

    // W -> fp16: wq into slot 0, wkv into slots 1,2
    w2f16_kernel<<<dim3(144, 1, 1), 256>>>(wq,  0LL, CDIM * CDIM, wqkv, 0LL);
    w2f16_kernel<<<dim3(288, 1, 1), 256>>>(wkv, 0LL, 2 * CDIM * CDIM,
                                           wqkv + CDIM * CDIM, 0LL);

    // pre (q | kv), contiguous scratch
    hmma_gemm_kernel<<<dim3(1024, 1, BSZ), 256, GEMM_SMEM>>>(
        x, (long long)CDIM * HWSZ, wqkv, 0LL,
        pre, (long long)3 * CDIM * HWSZ);
    hmma_gemm_kernel<<<dim3(1024, 2, BSZ), 256, GEMM_SMEM>>>(
        x_ref, (long long)CDIM * HWSZ, wqkv + CDIM * CDIM, 0LL,
        pre + (size_t)CDIM * HWSZ, (long long)3 * CDIM * HWSZ);

    dw_reduce_kernel<<<dim3(16, 16, BSZ * NHEADS), 256, smem2>>>(
        pre, wq_dw, wkv_dw, vh, ssq, ssk, gram);

    attn_proj_kernel<<<BSZ, 256>>>(gram, ssq, ssk, temp, wproj, Mm);

    // M -> fp16, then out = M_b @ v  (1-pass fp16 GEMM)
    w2f16_kernel<<<dim3(144, 1, BSZ), 256>>>(Mm, (long long)CDIM * CDIM,
                                             CDIM * CDIM, whm,
                                             (long long)CDIM * CDIM);
    hmma_gemm_h_kernel<<<dim3(1024, 1, BSZ), 256, GEMM_SMEM_H>>>(
        vh, (long long)CDIM * HWSZ, whm, (long long)CDIM * CDIM,
        out, (long long)CDIM * HWSZ);
}

// round 15
// speedup vs baseline: 1.2515x; 1.0660x over previous
#include <cuda_runtime.h>
#include <cuda_fp16.h>
#include <cstdint>

#define HWSZ  65536
#define CDIM  192
#define NHEADS 8
#define CH    24
#define BSZ   2
#define QP2   260

// ---------------- scratch (no cudaMalloc allowed) ----------------
__device__ float  g_pre [(size_t)BSZ * 3 * CDIM * HWSZ];   // q | k | v-pre
__device__ __half g_vh  [(size_t)BSZ * CDIM     * HWSZ];   // v in fp16
__device__ float  g_gram[BSZ * NHEADS * CH * CH];
__device__ float  g_ssq [BSZ * CDIM];
__device__ float  g_ssk [BSZ * CDIM];
__device__ float  g_M   [BSZ * CDIM * CDIM];

// fp16 weights: slot 0 = wq, slots 1,2 = wkv   (row-major [rows][192])
__device__ __half g_wqkv[3 * CDIM * CDIM];
__device__ __half g_whm [BSZ * CDIM * CDIM];

__device__ __forceinline__ uint32_t smem_u32(const void* p) {
    uint32_t a;
    asm("{ .reg .u64 t; cvta.to.shared.u64 t, %1; cvt.u32.u64 %0, t; }" : "=r"(a) : "l"(p));
    return a;
}
__device__ __forceinline__ void cpa16(uint32_t dst, const void* src) {
    asm volatile("cp.async.cg.shared.global [%0], [%1], 16;" :: "r"(dst), "l"(src));
}
#define CPA_COMMIT() asm volatile("cp.async.commit_group;" ::: "memory")
#define CPA_WAIT(n)  asm volatile("cp.async.wait_group %0;" :: "n"(n) : "memory")

// ---------------- zero accumulators ----------------
__global__ void zero_stats_kernel(float* gram, float* ssq, float* ssk) {
    int i = blockIdx.x * 256 + threadIdx.x;
    if (i < BSZ * NHEADS * CH * CH) gram[i] = 0.f;
    if (i < BSZ * CDIM) { ssq[i] = 0.f; ssk[i] = 0.f; }
}

// ---------------- prep: fp32 W -> fp16 ----------------
__global__ void w2f16_kernel(const float* __restrict__ W, long long wstride_b,
                             int total, __half* __restrict__ out, long long ostride_b) {
    int b = blockIdx.z;
    int i = blockIdx.x * 256 + threadIdx.x;
    if (i >= total) return;
    out[(size_t)b * ostride_b + i] = __float2half_rn(W[(size_t)b * wstride_b + i]);
}

// ================= pipelined HMMA fp16 2-pass GEMM, BK=32 (fp32 X) =================
#define AST 40
#define BST 72
#define OFF_W(s)  ((s) * 7680)
#define OFF_XH(s) (23040 + (s) * 4608)
#define OFF_XL(s) (23040 + (s) * 4608 + 2304)
#define GEMM_SMEM (32256 * 2)

__global__ __launch_bounds__(256, 2) void hmma_gemm_kernel(
    const float* __restrict__ X, long long xstride_b,
    const __half* __restrict__ Wh, long long wstride_b,
    float* __restrict__ Y, long long ystride_b)
{
    extern __shared__ __half sms[];
    const uint32_t sb = smem_u32(sms);

    const int tid = threadIdx.x;
    const int lid = tid & 31;
    const int wid = tid >> 5;
    const int wm  = wid >> 1;
    const int wn  = wid & 1;
    const int p0  = blockIdx.x * 64;
    const int nt  = blockIdx.y;
    const int b   = blockIdx.z;

    const float* Xb = X + (size_t)b * xstride_b + p0;
    const __half* WhB = Wh + (size_t)b * wstride_b + (size_t)nt * 192 * 192;

    float acc[3][4][4];
#pragma unroll
    for (int i = 0; i < 3; i++)
#pragma unroll
        for (int j = 0; j < 4; j++)
#pragma unroll
            for (int r = 0; r < 4; r++) acc[i][j][r] = 0.f;

    const int xrow = tid >> 4, xc4 = (tid & 15) << 2;
    const int arow = (lid & 7) + ((lid >> 3) & 1) * 8;
    const int acol = (lid >> 4) * 8;
    const int brow = arow;
    const int bcoff = ((lid >> 4) & 1) * 8;

#pragma unroll
    for (int s = 0; s < 2; s++) {
#pragma unroll
        for (int j = 0; j < 3; j++) {
            int idx = tid + j * 256;
            int row = idx >> 2;
            int c8  = (idx & 3) << 3;
            cpa16(sb + (uint32_t)((OFF_W(s) + row * AST + c8) * 2),
                  WhB + (size_t)row * 192 + s * 32 + c8);
        }
        CPA_COMMIT();
    }
    float4 xv0 = *reinterpret_cast<const float4*>(Xb + (size_t)xrow * HWSZ + xc4);
    float4 xv1 = *reinterpret_cast<const float4*>(Xb + (size_t)(xrow + 16) * HWSZ + xc4);

#pragma unroll 1
    for (int it = 0; it < 6; it++) {
        const int ws = it % 3;
        const int xs = it & 1;

#pragma unroll
        for (int hlf = 0; hlf < 2; hlf++) {
            float4 v = hlf ? xv1 : xv0;
            int row = xrow + hlf * 16;
            __half hx = __float2half_rn(v.x), hy = __float2half_rn(v.y);
            __half hz = __float2half_rn(v.z), hw = __float2half_rn(v.w);
            uint32_t h01 = (uint32_t)__half_as_ushort(hx)
                         | ((uint32_t)__half_as_ushort(hy) << 16);
            uint32_t h23 = (uint32_t)__half_as_ushort(hz)
                         | ((uint32_t)__half_as_ushort(hw) << 16);
            __half lx = __float2half_rn(v.x - __half2float(hx));
            __half ly = __float2half_rn(v.y - __half2float(hy));
            __half lz = __float2half_rn(v.z - __half2float(hz));
            __half lw = __float2half_rn(v.w - __half2float(hw));
            uint32_t l01 = (uint32_t)__half_as_ushort(lx)
                         | ((uint32_t)__half_as_ushort(ly) << 16);
            uint32_t l23 = (uint32_t)__half_as_ushort(lz)
                         | ((uint32_t)__half_as_ushort(lw) << 16);
            uint32_t xh = sb + (uint32_t)((OFF_XH(xs) + row * BST + xc4) * 2);
            uint32_t xl = sb + (uint32_t)((OFF_XL(xs) + row * BST + xc4) * 2);
            asm volatile("st.shared.v2.u32 [%0], {%1, %2};" :: "r"(xh), "r"(h01), "r"(h23));
            asm volatile("st.shared.v2.u32 [%0], {%1, %2};" :: "r"(xl), "r"(l01), "r"(l23));
        }

        if (it < 5) { CPA_WAIT(1); } else { CPA_WAIT(0); }
        __syncthreads();

        if (it < 4) {
            int s = it + 2, ss = s % 3;
#pragma unroll
            for (int j = 0; j < 3; j++) {
                int idx = tid + j * 256;
                int row = idx >> 2;
                int c8  = (idx & 3) << 3;
                cpa16(sb + (uint32_t)((OFF_W(ss) + row * AST + c8) * 2),
                      WhB + (size_t)row * 192 + s * 32 + c8);
            }
            CPA_COMMIT();
        }
        if (it < 5) {
            xv0 = *reinterpret_cast<const float4*>(
                Xb + (size_t)((it + 1) * 32 + xrow) * HWSZ + xc4);
            xv1 = *reinterpret_cast<const float4*>(
                Xb + (size_t)((it + 1) * 32 + xrow + 16) * HWSZ + xc4);
        }

        uint32_t ah[2][3][4], bh[2][2][4], bl[2][2][4];
#pragma unroll
        for (int kh = 0; kh < 2; kh++) {
#pragma unroll
            for (int mi = 0; mi < 3; mi++) {
                int r = wm * 48 + mi * 16 + arow;
                uint32_t addr = sb + (uint32_t)((OFF_W(ws) + r * AST + kh * 16 + acol) * 2);
                asm volatile("ldmatrix.sync.aligned.m8n8.x4.shared.b16 {%0,%1,%2,%3}, [%4];"
                    : "=r"(ah[kh][mi][0]), "=r"(ah[kh][mi][1]),
                      "=r"(ah[kh][mi][2]), "=r"(ah[kh][mi][3]) : "r"(addr));
            }
#pragma unroll
            for (int blk = 0; blk < 2; blk++) {
                int col = wn * 32 + blk * 16 + bcoff;
                int krow = kh * 16 + brow;
                uint32_t addr_h = sb + (uint32_t)((OFF_XH(xs) + krow * BST + col) * 2);
                uint32_t addr_l = sb + (uint32_t)((OFF_XL(xs) + krow * BST + col) * 2);
                asm volatile("ldmatrix.sync.aligned.m8n8.x4.trans.shared.b16 {%0,%1,%2,%3}, [%4];"
                    : "=r"(bh[kh][blk][0]), "=r"(bh[kh][blk][1]),
                      "=r"(bh[kh][blk][2]), "=r"(bh[kh][blk][3]) : "r"(addr_h));
                asm volatile("ldmatrix.sync.aligned.m8n8.x4.trans.shared.b16 {%0,%1,%2,%3}, [%4];"
                    : "=r"(bl[kh][blk][0]), "=r"(bl[kh][blk][1]),
                      "=r"(bl[kh][blk][2]), "=r"(bl[kh][blk][3]) : "r"(addr_l));
            }
        }

#define MMA(C, A, B0, B1) \
    asm volatile("mma.sync.aligned.m16n8k16.row.col.f32.f16.f16.f32 " \
        "{%0,%1,%2,%3}, {%4,%5,%6,%7}, {%8,%9}, {%0,%1,%2,%3};" \
        : "+f"((C)[0]), "+f"((C)[1]), "+f"((C)[2]), "+f"((C)[3]) \
        : "r"((A)[0]), "r"((A)[1]), "r"((A)[2]), "r"((A)[3]), "r"(B0), "r"(B1))

#pragma unroll
        for (int kh = 0; kh < 2; kh++)
#pragma unroll
            for (int mi = 0; mi < 3; mi++)
#pragma unroll
                for (int ni = 0; ni < 4; ni++) {
                    int blk = ni >> 1, hf = (ni & 1) << 1;
                    MMA(acc[mi][ni], ah[kh][mi], bh[kh][blk][hf], bh[kh][blk][hf + 1]);
                    MMA(acc[mi][ni], ah[kh][mi], bl[kh][blk][hf], bl[kh][blk][hf + 1]);
                }
        __syncthreads();
    }

    float* Yb = Y + (size_t)b * ystride_b + (size_t)nt * 192 * HWSZ + p0;
#pragma unroll
    for (int mi = 0; mi < 3; mi++) {
        int r0 = wm * 48 + mi * 16 + (lid >> 2);
#pragma unroll
        for (int ni = 0; ni < 4; ni++) {
            int px = wn * 32 + ni * 8 + (lid & 3) * 2;
            *reinterpret_cast<float2*>(Yb + (size_t)r0 * HWSZ + px) =
                make_float2(acc[mi][ni][0], acc[mi][ni][1]);
            *reinterpret_cast<float2*>(Yb + (size_t)(r0 + 8) * HWSZ + px) =
                make_float2(acc[mi][ni][2], acc[mi][ni][3]);
        }
    }
}

// ================= 1-pass HMMA GEMM, fp16 X (for out = M @ v) =================
#define OFF_X1(s) (23040 + (s) * 2304)
#define GEMM_SMEM_H ((23040 + 2 * 2304) * 2)   // 55296 B

__global__ __launch_bounds__(256, 2) void hmma_gemm_h_kernel(
    const __half* __restrict__ X, long long xstride_b,
    const __half* __restrict__ Wh, long long wstride_b,
    float* __restrict__ Y, long long ystride_b)
{
    extern __shared__ __half sms[];
    const uint32_t sb = smem_u32(sms);

    const int tid = threadIdx.x;
    const int lid = tid & 31;
    const int wid = tid >> 5;
    const int wm  = wid >> 1;
    const int wn  = wid & 1;
    const int p0  = blockIdx.x * 64;
    const int b   = blockIdx.z;

    const __half* Xb = X + (size_t)b * xstride_b + p0;
    const __half* WhB = Wh + (size_t)b * wstride_b;

    float acc[3][4][4];
#pragma unroll
    for (int i = 0; i < 3; i++)
#pragma unroll
        for (int j = 0; j < 4; j++)
#pragma unroll
            for (int r = 0; r < 4; r++) acc[i][j][r] = 0.f;

    const int xrow = tid >> 3, xc8 = (tid & 7) << 3;
    const int arow = (lid & 7) + ((lid >> 3) & 1) * 8;
    const int acol = (lid >> 4) * 8;
    const int brow = arow;
    const int bcoff = ((lid >> 4) & 1) * 8;

#pragma unroll
    for (int s = 0; s < 2; s++) {
#pragma unroll
        for (int j = 0; j < 3; j++) {
            int idx = tid + j * 256;
            int row = idx >> 2;
            int c8  = (idx & 3) << 3;
            cpa16(sb + (uint32_t)((OFF_W(s) + row * AST + c8) * 2),
                  WhB + (size_t)row * 192 + s * 32 + c8);
        }
        CPA_COMMIT();
    }
    uint4 xv = *reinterpret_cast<const uint4*>(Xb + (size_t)xrow * HWSZ + xc8);

#pragma unroll 1
    for (int it = 0; it < 6; it++) {
        const int ws = it % 3;
        const int xs = it & 1;

        {
            uint32_t xa = sb + (uint32_t)((OFF_X1(xs) + xrow * BST + xc8) * 2);
            asm volatile("st.shared.v4.u32 [%0], {%1, %2, %3, %4};"
                :: "r"(xa), "r"(xv.x), "r"(xv.y), "r"(xv.z), "r"(xv.w));
        }

        if (it < 5) { CPA_WAIT(1); } else { CPA_WAIT(0); }
        __syncthreads();

        if (it < 4) {
            int s = it + 2, ss = s % 3;
#pragma unroll
            for (int j = 0; j < 3; j++) {
                int idx = tid + j * 256;
                int row = idx >> 2;
                int c8  = (idx & 3) << 3;
                cpa16(sb + (uint32_t)((OFF_W(ss) + row * AST + c8) * 2),
                      WhB + (size_t)row * 192 + s * 32 + c8);
            }
            CPA_COMMIT();
        }
        if (it < 5)
            xv = *reinterpret_cast<const uint4*>(
                Xb + (size_t)((it + 1) * 32 + xrow) * HWSZ + xc8);

        uint32_t ah[2][3][4], bh[2][2][4];
#pragma unroll
        for (int kh = 0; kh < 2; kh++) {
#pragma unroll
            for (int mi = 0; mi < 3; mi++) {
                int r = wm * 48 + mi * 16 + arow;
                uint32_t addr = sb + (uint32_t)((OFF_W(ws) + r * AST + kh * 16 + acol) * 2);
                asm volatile("ldmatrix.sync.aligned.m8n8.x4.shared.b16 {%0,%1,%2,%3}, [%4];"
                    : "=r"(ah[kh][mi][0]), "=r"(ah[kh][mi][1]),
                      "=r"(ah[kh][mi][2]), "=r"(ah[kh][mi][3]) : "r"(addr));
            }
#pragma unroll
            for (int blk = 0; blk < 2; blk++) {
                int col = wn * 32 + blk * 16 + bcoff;
                int krow = kh * 16 + brow;
                uint32_t addr = sb + (uint32_t)((OFF_X1(xs) + krow * BST + col) * 2);
                asm volatile("ldmatrix.sync.aligned.m8n8.x4.trans.shared.b16 {%0,%1,%2,%3}, [%4];"
                    : "=r"(bh[kh][blk][0]), "=r"(bh[kh][blk][1]),
                      "=r"(bh[kh][blk][2]), "=r"(bh[kh][blk][3]) : "r"(addr));
            }
        }

#pragma unroll
        for (int kh = 0; kh < 2; kh++)
#pragma unroll
            for (int mi = 0; mi < 3; mi++)
#pragma unroll
                for (int ni = 0; ni < 4; ni++) {
                    int blk = ni >> 1, hf = (ni & 1) << 1;
                    MMA(acc[mi][ni], ah[kh][mi], bh[kh][blk][hf], bh[kh][blk][hf + 1]);
                }
        __syncthreads();
    }

    float* Yb = Y + (size_t)b * ystride_b + p0;
#pragma unroll
    for (int mi = 0; mi < 3; mi++) {
        int r0 = wm * 48 + mi * 16 + (lid >> 2);
#pragma unroll
        for (int ni = 0; ni < 4; ni++) {
            int px = wn * 32 + ni * 8 + (lid & 3) * 2;
            *reinterpret_cast<float2*>(Yb + (size_t)r0 * HWSZ + px) =
                make_float2(acc[mi][ni][0], acc[mi][ni][1]);
            *reinterpret_cast<float2*>(Yb + (size_t)(r0 + 8) * HWSZ + px) =
                make_float2(acc[mi][ni][2], acc[mi][ni][3]);
        }
    }
}

// ---------------- dwconv3x3 + Gram + norms + v (double-buffered halo) ----------------
__device__ __forceinline__ float4 dw_quad(const float* hb, const float* wr) {
    float r4[4][4];
#pragma unroll
    for (int r = 0; r < 4; r++) {
        float2 a  = *reinterpret_cast<const float2*>(hb + r * 20);
        float2 b2 = *reinterpret_cast<const float2*>(hb + r * 20 + 2);
        r4[r][0] = a.x; r4[r][1] = a.y; r4[r][2] = b2.x; r4[r][3] = b2.y;
    }
    float ox = 0.f, oy = 0.f, oz = 0.f, ow = 0.f;
#pragma unroll
    for (int i2 = 0; i2 < 3; i2++)
#pragma unroll
        for (int j2 = 0; j2 < 3; j2++) {
            float wv = wr[i2 * 3 + j2];
            ox += r4[i2][j2]     * wv;
            oy += r4[i2][j2 + 1] * wv;
            oz += r4[i2 + 1][j2] * wv;
            ow += r4[i2 + 1][j2 + 1] * wv;
        }
    return make_float4(ox, oy, oz, ow);
}

// smem: halo[2*2880] + qs[24*QP2] + ks[24*QP2] = 72960 B -> 3 CTAs/SM
__global__ __launch_bounds__(256, 3) void dw_reduce_kernel(
    const float* __restrict__ pre, const float* __restrict__ wq_dw,
    const float* __restrict__ wkv_dw,
    __half* __restrict__ vout, float* __restrict__ ssq, float* __restrict__ ssk,
    float* __restrict__ gram)
{
    extern __shared__ float sm[];
    float* halo = sm;                  // 2 x 2880 floats
    float* qs   = sm + 5760;
    float* ks   = qs + 24 * QP2;

    const int tid = threadIdx.x;
    const int b   = blockIdx.z >> 3;
    const int h   = blockIdx.z & 7;
    const int cb  = h * CH;
    const int tx0 = blockIdx.x * 16;
    const int ty0 = blockIdx.y * 16;

    const int cs = tid >> 6;
    const int qd = tid & 63;
    const int qy = qd >> 3, qx = qd & 7;
    const int hoff = (2 * qy) * 20 + 2 * qx;

    const float* base = pre + (size_t)b * 3 * CDIM * HWSZ;

    // per-thread halo index precompute (i = tid + j*256 over 8*324 = 2592 elems)
    int goff[11], hloc[11];
    bool val[11];
#pragma unroll
    for (int j = 0; j < 11; j++) {
        int i = tid + j * 256;
        if (i < 2592) {
            int ch  = i / 324;
            int rem = i - ch * 324;
            int rr  = rem / 18;
            int ccx = rem - rr * 18;
            int gy = ty0 - 1 + rr, gx = tx0 - 1 + ccx;
            val[j]  = ((unsigned)gy < 256u) && ((unsigned)gx < 256u);
            goff[j] = ch * HWSZ + gy * 256 + gx;
            hloc[j] = ch * 360 + rr * 20 + ccx;
        } else { val[j] = false; goff[j] = 0; hloc[j] = -1; }
    }

    // prologue: stage group 0 (q, sg=0) into halo buffer 0
    {
        const float* s0 = base + (size_t)cb * HWSZ;
#pragma unroll
        for (int j = 0; j < 11; j++)
            if (hloc[j] >= 0)
                halo[hloc[j]] = val[j] ? __ldg(s0 + goff[j]) : 0.f;
    }
    __syncthreads();

    // 9 groups: g 0-2 q, 3-5 k, 6-8 v. One sync per group; prefetch g+1 in regs.
    float rn[11];
#pragma unroll 1
    for (int g = 0; g < 9; g++) {
        const int t  = g / 3;
        const int sg = g - t * 3;

        // prefetch group g+1 (LDG early, consumed after compute)
        if (g < 8) {
            int gn = g + 1, tn = gn / 3, sgn = gn - tn * 3;
            const float* sn = base + (size_t)(tn * CDIM + cb + sgn * 8) * HWSZ;
#pragma unroll
            for (int j = 0; j < 11; j++)
                rn[j] = (hloc[j] >= 0 && val[j]) ? __ldg(sn + goff[j]) : 0.f;
        }

        // compute group g from halo[g&1]
        const float* hb = halo + (g & 1) * 2880;
#pragma unroll
        for (int it = 0; it < 2; it++) {
            int cc = cs + it * 4;
            int c  = sg * 8 + cc;
            const float* w = (t == 0) ? wq_dw + (size_t)(cb + c) * 9
                           : (t == 1) ? wkv_dw + (size_t)(cb + c) * 9
                                      : wkv_dw + (size_t)(CDIM + cb + c) * 9;
            float wr[9];
#pragma unroll
            for (int j = 0; j < 9; j++) wr[j] = __ldg(w + j);
            float4 o = dw_quad(hb + cc * 360 + hoff, wr);
            if (t == 0) {
                *reinterpret_cast<float4*>(qs + c * QP2 + qd * 4) = o;
            } else if (t == 1) {
                *reinterpret_cast<float4*>(ks + c * QP2 + qd * 4) = o;
            } else {
                __half* dst = vout + ((size_t)b * CDIM + cb + c) * HWSZ
                            + (ty0 + 2 * qy) * 256 + (tx0 + 2 * qx);
                uint32_t p0w = (uint32_t)__half_as_ushort(__float2half_rn(o.x))
                             | ((uint32_t)__half_as_ushort(__float2half_rn(o.y)) << 16);
                uint32_t p1w = (uint32_t)__half_as_ushort(__float2half_rn(o.z))
                             | ((uint32_t)__half_as_ushort(__float2half_rn(o.w)) << 16);
                *reinterpret_cast<uint32_t*>(dst)       = p0w;
                *reinterpret_cast<uint32_t*>(dst + 256) = p1w;
            }
        }

        // stage group g+1 into the other buffer
        if (g < 8) {
            float* hn = halo + ((g + 1) & 1) * 2880;
#pragma unroll
            for (int j = 0; j < 11; j++)
                if (hloc[j] >= 0) hn[hloc[j]] = rn[j];
        }
        __syncthreads();
    }

    // ---- sum of squares ----
    if (tid < 192) {
        int c = tid >> 3, s = tid & 7;
        float sq = 0.f, sk = 0.f;
#pragma unroll
        for (int i = 0; i < 8; i++) {
            int j = s + (i << 3);
            float4 a = *reinterpret_cast<const float4*>(qs + c * QP2 + 4 * j);
            sq += a.x * a.x + a.y * a.y + a.z * a.z + a.w * a.w;
            float4 kk = *reinterpret_cast<const float4*>(ks + c * QP2 + 4 * j);
            sk += kk.x * kk.x + kk.y * kk.y + kk.z * kk.z + kk.w * kk.w;
        }
#pragma unroll
        for (int off = 1; off < 8; off <<= 1) {
            sq += __shfl_xor_sync(0xffffffffu, sq, off);
            sk += __shfl_xor_sync(0xffffffffu, sk, off);
        }
        if (s == 0) {
            atomicAdd(&ssq[b * CDIM + cb + c], sq);
            atomicAdd(&ssk[b * CDIM + cb + c], sk);
        }
    }

    // ---- Gram ----
#pragma unroll 1
    for (int t = tid; t < 288; t += 256) {
        int e = t >> 3, s = t & 7;
        int c0 = (e / 6) * 4, d0 = (e % 6) * 4;
        float acc[16];
#pragma unroll
        for (int j = 0; j < 16; j++) acc[j] = 0.f;
#pragma unroll 2
        for (int i = 0; i < 8; i++) {
            int j = s + (i << 3);
            float4 qv[4], kv[4];
#pragma unroll
            for (int r = 0; r < 4; r++) {
                qv[r] = *reinterpret_cast<const float4*>(qs + (c0 + r) * QP2 + 4 * j);
                kv[r] = *reinterpret_cast<const float4*>(ks + (d0 + r) * QP2 + 4 * j);
            }
#pragma unroll
            for (int a = 0; a < 4; a++)
#pragma unroll
                for (int d = 0; d < 4; d++)
                    acc[a * 4 + d] += qv[a].x * kv[d].x + qv[a].y * kv[d].y
                                    + qv[a].z * kv[d].z + qv[a].w * kv[d].w;
        }
#pragma unroll
        for (int off = 1; off < 8; off <<= 1)
#pragma unroll
            for (int j = 0; j < 16; j++)
                acc[j] += __shfl_xor_sync(0xffffffffu, acc[j], off);
        if (s == 0) {
            float* gb = gram + (((size_t)b * NHEADS + h) * CH + c0) * CH + d0;
#pragma unroll
            for (int jq = 0; jq < 4; jq++)
#pragma unroll
                for (int jk = 0; jk < 4; jk++)
                    atomicAdd(&gb[jq * CH + jk], acc[jq * 4 + jk]);
        }
    }
}

// ---------------- softmax + M = Wproj * blockdiag(attn) ----------------
__global__ __launch_bounds__(256) void attn_proj_kernel(
    const float* __restrict__ gram, const float* __restrict__ ssq,
    const float* __restrict__ ssk,  const float* __restrict__ temp,
    const float* __restrict__ wproj, float* __restrict__ Mout)
{
    __shared__ float at[192][25];
    __shared__ float nk_s[192];
    const int b = blockIdx.x, tid = threadIdx.x;

    if (tid < 192) nk_s[tid] = fmaxf(sqrtf(ssk[b * CDIM + tid]), 1e-12f);
    __syncthreads();

    if (tid < 192) {
        int h = tid / 24, c = tid % 24;
        float nq = fmaxf(sqrtf(ssq[b * CDIM + tid]), 1e-12f);
        float tv = temp[h];
        const float* gr = gram + (((size_t)b * NHEADS + h) * CH + c) * CH;
        float vals[24];
        float mx = -1e30f;
#pragma unroll
        for (int d = 0; d < 24; d++) {
            float v = gr[d] / (nq * nk_s[h * 24 + d]) * tv;
            vals[d] = v;
            mx = fmaxf(mx, v);
        }
        float s = 0.f;
#pragma unroll
        for (int d = 0; d < 24; d++) { vals[d] = expf(vals[d] - mx); s += vals[d]; }
        float inv = 1.f / s;
#pragma unroll
        for (int d = 0; d < 24; d++) at[tid][d] = vals[d] * inv;
    }
    __syncthreads();

    for (int idx = tid; idx < 192 * 192; idx += 256) {
        int o = idx / 192, dg = idx % 192;
        int h = dg / 24, d = dg % 24;
        float s = 0.f;
#pragma unroll
        for (int c = 0; c < 24; c++)
            s += wproj[o * 192 + h * 24 + c] * at[h * 24 + c][d];
        Mout[(size_t)b * CDIM * CDIM + idx] = s;
    }
}

// ---------------- launch ----------------
extern "C" void kernel_launch(void* const* d_in, const int* in_sizes, int n_in,
                              void* d_out, int out_size) {
    const float* x      = (const float*)d_in[0];
    const float* x_ref  = (const float*)d_in[1];
    const float* wq     = (const float*)d_in[2];
    const float* wq_dw  = (const float*)d_in[3];
    const float* wkv    = (const float*)d_in[4];
    const float* wkv_dw = (const float*)d_in[5];
    const float* wproj  = (const float*)d_in[6];
    const float* temp   = (const float*)d_in[7];
    float* out = (float*)d_out;

    float *pre, *gram, *ssq, *ssk, *Mm;
    __half *vh, *wqkv, *whm;
    cudaGetSymbolAddress((void**)&pre,  g_pre);
    cudaGetSymbolAddress((void**)&vh,   g_vh);
    cudaGetSymbolAddress((void**)&gram, g_gram);
    cudaGetSymbolAddress((void**)&ssq,  g_ssq);
    cudaGetSymbolAddress((void**)&ssk,  g_ssk);
    cudaGetSymbolAddress((void**)&Mm,   g_M);
    cudaGetSymbolAddress((void**)&wqkv, g_wqkv);
    cudaGetSymbolAddress((void**)&whm,  g_whm);

    const int smem2 = (5760 + 2 * 24 * QP2) * (int)sizeof(float);   // 72960 B
    cudaFuncSetAttribute(dw_reduce_kernel,
                         cudaFuncAttributeMaxDynamicSharedMemorySize, smem2);
    cudaFuncSetAttribute(hmma_gemm_kernel,
                         cudaFuncAttributeMaxDynamicSharedMemorySize, GEMM_SMEM);
    cudaFuncSetAttribute(hmma_gemm_h_kernel,
                         cudaFuncAttributeMaxDynamicSharedMemorySize, GEMM_SMEM_H);

    zero_stats_kernel<<<36, 256>>>(gram, ssq, ssk);

    // W -> fp16: wq into slot 0, wkv into slots 1,2
    w2f16_kernel<<<dim3(144, 1, 1), 256>>>(wq,  0LL, CDIM * CDIM, wqkv, 0LL);
    w2f16_kernel<<<dim3(288, 1, 1), 256>>>(wkv, 0LL, 2 * CDIM * CDIM,
                                           wqkv + CDIM * CDIM, 0LL);

    // pre (q | kv), contiguous scratch
    hmma_gemm_kernel<<<dim3(1024, 1, BSZ), 256, GEMM_SMEM>>>(
        x, (long long)CDIM * HWSZ, wqkv, 0LL,
        pre, (long long)3 * CDIM * HWSZ);
    hmma_gemm_kernel<<<dim3(1024, 2, BSZ), 256, GEMM_SMEM>>>(
        x_ref, (long long)CDIM * HWSZ, wqkv + CDIM * CDIM, 0LL,
        pre + (size_t)CDIM * HWSZ, (long long)3 * CDIM * HWSZ);

    dw_reduce_kernel<<<dim3(16, 16, BSZ * NHEADS), 256, smem2>>>(
        pre, wq_dw, wkv_dw, vh, ssq, ssk, gram);

    attn_proj_kernel<<<BSZ, 256>>>(gram, ssq, ssk, temp, wproj, Mm);

    // M -> fp16, then out = M_b @ v  (1-pass fp16 GEMM)
    w2f16_kernel<<<dim3(144, 1, BSZ), 256>>>(Mm, (long long)CDIM * CDIM,
                                             CDIM * CDIM, whm,
                                             (long long)CDIM * CDIM);
    hmma_gemm_h_kernel<<<dim3(1024, 1, BSZ), 256, GEMM_SMEM_H>>>(
        vh, (long long)CDIM * HWSZ, whm, (long long)CDIM * CDIM,
        out, (long long)CDIM * HWSZ);
}

// round 16
// speedup vs baseline: 1.3066x; 1.0441x over previous
#include <cuda_runtime.h>
#include <cuda_fp16.h>
#include <cstdint>

#define HWSZ  65536
#define CDIM  192
#define NHEADS 8
#define CH    24
#define BSZ   2
#define QP2   260

// ---------------- scratch (no cudaMalloc allowed) ----------------
__device__ __half g_pre [(size_t)BSZ * 3 * CDIM * HWSZ];   // q | k | v-pre (fp16)
__device__ __half g_vh  [(size_t)BSZ * CDIM     * HWSZ];   // v in fp16
__device__ float  g_gram[BSZ * NHEADS * CH * CH];
__device__ float  g_ssq [BSZ * CDIM];
__device__ float  g_ssk [BSZ * CDIM];

// fp16 weights: slot 0 = wq, slots 1,2 = wkv   (row-major [rows][192])
__device__ __half g_wqkv[3 * CDIM * CDIM];
__device__ __half g_whm [BSZ * CDIM * CDIM];

__device__ __forceinline__ uint32_t smem_u32(const void* p) {
    uint32_t a;
    asm("{ .reg .u64 t; cvta.to.shared.u64 t, %1; cvt.u32.u64 %0, t; }" : "=r"(a) : "l"(p));
    return a;
}
__device__ __forceinline__ void cpa16(uint32_t dst, const void* src) {
    asm volatile("cp.async.cg.shared.global [%0], [%1], 16;" :: "r"(dst), "l"(src));
}
#define CPA_COMMIT() asm volatile("cp.async.commit_group;" ::: "memory")
#define CPA_WAIT(n)  asm volatile("cp.async.wait_group %0;" :: "n"(n) : "memory")

// ---------------- zero accumulators ----------------
__global__ void zero_stats_kernel(float* gram, float* ssq, float* ssk) {
    int i = blockIdx.x * 256 + threadIdx.x;
    if (i < BSZ * NHEADS * CH * CH) gram[i] = 0.f;
    if (i < BSZ * CDIM) { ssq[i] = 0.f; ssk[i] = 0.f; }
}

// ---------------- prep: fp32 W -> fp16 ----------------
__global__ void w2f16_kernel(const float* __restrict__ W, long long wstride_b,
                             int total, __half* __restrict__ out, long long ostride_b) {
    int b = blockIdx.z;
    int i = blockIdx.x * 256 + threadIdx.x;
    if (i >= total) return;
    out[(size_t)b * ostride_b + i] = __float2half_rn(W[(size_t)b * wstride_b + i]);
}

// ================= pipelined HMMA fp16 2-pass GEMM, BK=32, fp16 output =================
#define AST 40
#define BST 72
#define OFF_W(s)  ((s) * 7680)
#define OFF_XH(s) (23040 + (s) * 4608)
#define OFF_XL(s) (23040 + (s) * 4608 + 2304)
#define GEMM_SMEM (32256 * 2)

__global__ __launch_bounds__(256, 2) void hmma_gemm_kernel(
    const float* __restrict__ X, long long xstride_b,
    const __half* __restrict__ Wh, long long wstride_b,
    __half* __restrict__ Y, long long ystride_b)
{
    extern __shared__ __half sms[];
    const uint32_t sb = smem_u32(sms);

    const int tid = threadIdx.x;
    const int lid = tid & 31;
    const int wid = tid >> 5;
    const int wm  = wid >> 1;
    const int wn  = wid & 1;
    const int p0  = blockIdx.x * 64;
    const int nt  = blockIdx.y;
    const int b   = blockIdx.z;

    const float* Xb = X + (size_t)b * xstride_b + p0;
    const __half* WhB = Wh + (size_t)b * wstride_b + (size_t)nt * 192 * 192;

    float acc[3][4][4];
#pragma unroll
    for (int i = 0; i < 3; i++)
#pragma unroll
        for (int j = 0; j < 4; j++)
#pragma unroll
            for (int r = 0; r < 4; r++) acc[i][j][r] = 0.f;

    const int xrow = tid >> 4, xc4 = (tid & 15) << 2;
    const int arow = (lid & 7) + ((lid >> 3) & 1) * 8;
    const int acol = (lid >> 4) * 8;
    const int brow = arow;
    const int bcoff = ((lid >> 4) & 1) * 8;

#pragma unroll
    for (int s = 0; s < 2; s++) {
#pragma unroll
        for (int j = 0; j < 3; j++) {
            int idx = tid + j * 256;
            int row = idx >> 2;
            int c8  = (idx & 3) << 3;
            cpa16(sb + (uint32_t)((OFF_W(s) + row * AST + c8) * 2),
                  WhB + (size_t)row * 192 + s * 32 + c8);
        }
        CPA_COMMIT();
    }
    float4 xv0 = *reinterpret_cast<const float4*>(Xb + (size_t)xrow * HWSZ + xc4);
    float4 xv1 = *reinterpret_cast<const float4*>(Xb + (size_t)(xrow + 16) * HWSZ + xc4);

#pragma unroll 1
    for (int it = 0; it < 6; it++) {
        const int ws = it % 3;
        const int xs = it & 1;

#pragma unroll
        for (int hlf = 0; hlf < 2; hlf++) {
            float4 v = hlf ? xv1 : xv0;
            int row = xrow + hlf * 16;
            __half hx = __float2half_rn(v.x), hy = __float2half_rn(v.y);
            __half hz = __float2half_rn(v.z), hw = __float2half_rn(v.w);
            uint32_t h01 = (uint32_t)__half_as_ushort(hx)
                         | ((uint32_t)__half_as_ushort(hy) << 16);
            uint32_t h23 = (uint32_t)__half_as_ushort(hz)
                         | ((uint32_t)__half_as_ushort(hw) << 16);
            __half lx = __float2half_rn(v.x - __half2float(hx));
            __half ly = __float2half_rn(v.y - __half2float(hy));
            __half lz = __float2half_rn(v.z - __half2float(hz));
            __half lw = __float2half_rn(v.w - __half2float(hw));
            uint32_t l01 = (uint32_t)__half_as_ushort(lx)
                         | ((uint32_t)__half_as_ushort(ly) << 16);
            uint32_t l23 = (uint32_t)__half_as_ushort(lz)
                         | ((uint32_t)__half_as_ushort(lw) << 16);
            uint32_t xh = sb + (uint32_t)((OFF_XH(xs) + row * BST + xc4) * 2);
            uint32_t xl = sb + (uint32_t)((OFF_XL(xs) + row * BST + xc4) * 2);
            asm volatile("st.shared.v2.u32 [%0], {%1, %2};" :: "r"(xh), "r"(h01), "r"(h23));
            asm volatile("st.shared.v2.u32 [%0], {%1, %2};" :: "r"(xl), "r"(l01), "r"(l23));
        }

        if (it < 5) { CPA_WAIT(1); } else { CPA_WAIT(0); }
        __syncthreads();

        if (it < 4) {
            int s = it + 2, ss = s % 3;
#pragma unroll
            for (int j = 0; j < 3; j++) {
                int idx = tid + j * 256;
                int row = idx >> 2;
                int c8  = (idx & 3) << 3;
                cpa16(sb + (uint32_t)((OFF_W(ss) + row * AST + c8) * 2),
                      WhB + (size_t)row * 192 + s * 32 + c8);
            }
            CPA_COMMIT();
        }
        if (it < 5) {
            xv0 = *reinterpret_cast<const float4*>(
                Xb + (size_t)((it + 1) * 32 + xrow) * HWSZ + xc4);
            xv1 = *reinterpret_cast<const float4*>(
                Xb + (size_t)((it + 1) * 32 + xrow + 16) * HWSZ + xc4);
        }

        uint32_t ah[2][3][4], bh[2][2][4], bl[2][2][4];
#pragma unroll
        for (int kh = 0; kh < 2; kh++) {
#pragma unroll
            for (int mi = 0; mi < 3; mi++) {
                int r = wm * 48 + mi * 16 + arow;
                uint32_t addr = sb + (uint32_t)((OFF_W(ws) + r * AST + kh * 16 + acol) * 2);
                asm volatile("ldmatrix.sync.aligned.m8n8.x4.shared.b16 {%0,%1,%2,%3}, [%4];"
                    : "=r"(ah[kh][mi][0]), "=r"(ah[kh][mi][1]),
                      "=r"(ah[kh][mi][2]), "=r"(ah[kh][mi][3]) : "r"(addr));
            }
#pragma unroll
            for (int blk = 0; blk < 2; blk++) {
                int col = wn * 32 + blk * 16 + bcoff;
                int krow = kh * 16 + brow;
                uint32_t addr_h = sb + (uint32_t)((OFF_XH(xs) + krow * BST + col) * 2);
                uint32_t addr_l = sb + (uint32_t)((OFF_XL(xs) + krow * BST + col) * 2);
                asm volatile("ldmatrix.sync.aligned.m8n8.x4.trans.shared.b16 {%0,%1,%2,%3}, [%4];"
                    : "=r"(bh[kh][blk][0]), "=r"(bh[kh][blk][1]),
                      "=r"(bh[kh][blk][2]), "=r"(bh[kh][blk][3]) : "r"(addr_h));
                asm volatile("ldmatrix.sync.aligned.m8n8.x4.trans.shared.b16 {%0,%1,%2,%3}, [%4];"
                    : "=r"(bl[kh][blk][0]), "=r"(bl[kh][blk][1]),
                      "=r"(bl[kh][blk][2]), "=r"(bl[kh][blk][3]) : "r"(addr_l));
            }
        }

#define MMA(C, A, B0, B1) \
    asm volatile("mma.sync.aligned.m16n8k16.row.col.f32.f16.f16.f32 " \
        "{%0,%1,%2,%3}, {%4,%5,%6,%7}, {%8,%9}, {%0,%1,%2,%3};" \
        : "+f"((C)[0]), "+f"((C)[1]), "+f"((C)[2]), "+f"((C)[3]) \
        : "r"((A)[0]), "r"((A)[1]), "r"((A)[2]), "r"((A)[3]), "r"(B0), "r"(B1))

#pragma unroll
        for (int kh = 0; kh < 2; kh++)
#pragma unroll
            for (int mi = 0; mi < 3; mi++)
#pragma unroll
                for (int ni = 0; ni < 4; ni++) {
                    int blk = ni >> 1, hf = (ni & 1) << 1;
                    MMA(acc[mi][ni], ah[kh][mi], bh[kh][blk][hf], bh[kh][blk][hf + 1]);
                    MMA(acc[mi][ni], ah[kh][mi], bl[kh][blk][hf], bl[kh][blk][hf + 1]);
                }
        __syncthreads();
    }

    // epilogue: fp16 output (half2 per 2 pixels)
    __half* Yb = Y + (size_t)b * ystride_b + (size_t)nt * 192 * HWSZ + p0;
#pragma unroll
    for (int mi = 0; mi < 3; mi++) {
        int r0 = wm * 48 + mi * 16 + (lid >> 2);
#pragma unroll
        for (int ni = 0; ni < 4; ni++) {
            int px = wn * 32 + ni * 8 + (lid & 3) * 2;
            uint32_t w0 = (uint32_t)__half_as_ushort(__float2half_rn(acc[mi][ni][0]))
                        | ((uint32_t)__half_as_ushort(__float2half_rn(acc[mi][ni][1])) << 16);
            uint32_t w1 = (uint32_t)__half_as_ushort(__float2half_rn(acc[mi][ni][2]))
                        | ((uint32_t)__half_as_ushort(__float2half_rn(acc[mi][ni][3])) << 16);
            *reinterpret_cast<uint32_t*>(Yb + (size_t)r0 * HWSZ + px)       = w0;
            *reinterpret_cast<uint32_t*>(Yb + (size_t)(r0 + 8) * HWSZ + px) = w1;
        }
    }
}

// ================= 1-pass HMMA GEMM, fp16 X, fp32 out (out = M @ v) =================
#define OFF_X1(s) (23040 + (s) * 2304)
#define GEMM_SMEM_H ((23040 + 2 * 2304) * 2)   // 55296 B

__global__ __launch_bounds__(256, 2) void hmma_gemm_h_kernel(
    const __half* __restrict__ X, long long xstride_b,
    const __half* __restrict__ Wh, long long wstride_b,
    float* __restrict__ Y, long long ystride_b)
{
    extern __shared__ __half sms[];
    const uint32_t sb = smem_u32(sms);

    const int tid = threadIdx.x;
    const int lid = tid & 31;
    const int wid = tid >> 5;
    const int wm  = wid >> 1;
    const int wn  = wid & 1;
    const int p0  = blockIdx.x * 64;
    const int b   = blockIdx.z;

    const __half* Xb = X + (size_t)b * xstride_b + p0;
    const __half* WhB = Wh + (size_t)b * wstride_b;

    float acc[3][4][4];
#pragma unroll
    for (int i = 0; i < 3; i++)
#pragma unroll
        for (int j = 0; j < 4; j++)
#pragma unroll
            for (int r = 0; r < 4; r++) acc[i][j][r] = 0.f;

    const int xrow = tid >> 3, xc8 = (tid & 7) << 3;
    const int arow = (lid & 7) + ((lid >> 3) & 1) * 8;
    const int acol = (lid >> 4) * 8;
    const int brow = arow;
    const int bcoff = ((lid >> 4) & 1) * 8;

#pragma unroll
    for (int s = 0; s < 2; s++) {
#pragma unroll
        for (int j = 0; j < 3; j++) {
            int idx = tid + j * 256;
            int row = idx >> 2;
            int c8  = (idx & 3) << 3;
            cpa16(sb + (uint32_t)((OFF_W(s) + row * AST + c8) * 2),
                  WhB + (size_t)row * 192 + s * 32 + c8);
        }
        CPA_COMMIT();
    }
    uint4 xv = *reinterpret_cast<const uint4*>(Xb + (size_t)xrow * HWSZ + xc8);

#pragma unroll 1
    for (int it = 0; it < 6; it++) {
        const int ws = it % 3;
        const int xs = it & 1;

        {
            uint32_t xa = sb + (uint32_t)((OFF_X1(xs) + xrow * BST + xc8) * 2);
            asm volatile("st.shared.v4.u32 [%0], {%1, %2, %3, %4};"
                :: "r"(xa), "r"(xv.x), "r"(xv.y), "r"(xv.z), "r"(xv.w));
        }

        if (it < 5) { CPA_WAIT(1); } else { CPA_WAIT(0); }
        __syncthreads();

        if (it < 4) {
            int s = it + 2, ss = s % 3;
#pragma unroll
            for (int j = 0; j < 3; j++) {
                int idx = tid + j * 256;
                int row = idx >> 2;
                int c8  = (idx & 3) << 3;
                cpa16(sb + (uint32_t)((OFF_W(ss) + row * AST + c8) * 2),
                      WhB + (size_t)row * 192 + s * 32 + c8);
            }
            CPA_COMMIT();
        }
        if (it < 5)
            xv = *reinterpret_cast<const uint4*>(
                Xb + (size_t)((it + 1) * 32 + xrow) * HWSZ + xc8);

        uint32_t ah[2][3][4], bh[2][2][4];
#pragma unroll
        for (int kh = 0; kh < 2; kh++) {
#pragma unroll
            for (int mi = 0; mi < 3; mi++) {
                int r = wm * 48 + mi * 16 + arow;
                uint32_t addr = sb + (uint32_t)((OFF_W(ws) + r * AST + kh * 16 + acol) * 2);
                asm volatile("ldmatrix.sync.aligned.m8n8.x4.shared.b16 {%0,%1,%2,%3}, [%4];"
                    : "=r"(ah[kh][mi][0]), "=r"(ah[kh][mi][1]),
                      "=r"(ah[kh][mi][2]), "=r"(ah[kh][mi][3]) : "r"(addr));
            }
#pragma unroll
            for (int blk = 0; blk < 2; blk++) {
                int col = wn * 32 + blk * 16 + bcoff;
                int krow = kh * 16 + brow;
                uint32_t addr = sb + (uint32_t)((OFF_X1(xs) + krow * BST + col) * 2);
                asm volatile("ldmatrix.sync.aligned.m8n8.x4.trans.shared.b16 {%0,%1,%2,%3}, [%4];"
                    : "=r"(bh[kh][blk][0]), "=r"(bh[kh][blk][1]),
                      "=r"(bh[kh][blk][2]), "=r"(bh[kh][blk][3]) : "r"(addr));
            }
        }

#pragma unroll
        for (int kh = 0; kh < 2; kh++)
#pragma unroll
            for (int mi = 0; mi < 3; mi++)
#pragma unroll
                for (int ni = 0; ni < 4; ni++) {
                    int blk = ni >> 1, hf = (ni & 1) << 1;
                    MMA(acc[mi][ni], ah[kh][mi], bh[kh][blk][hf], bh[kh][blk][hf + 1]);
                }
        __syncthreads();
    }

    float* Yb = Y + (size_t)b * ystride_b + p0;
#pragma unroll
    for (int mi = 0; mi < 3; mi++) {
        int r0 = wm * 48 + mi * 16 + (lid >> 2);
#pragma unroll
        for (int ni = 0; ni < 4; ni++) {
            int px = wn * 32 + ni * 8 + (lid & 3) * 2;
            *reinterpret_cast<float2*>(Yb + (size_t)r0 * HWSZ + px) =
                make_float2(acc[mi][ni][0], acc[mi][ni][1]);
            *reinterpret_cast<float2*>(Yb + (size_t)(r0 + 8) * HWSZ + px) =
                make_float2(acc[mi][ni][2], acc[mi][ni][3]);
        }
    }
}

// ---------------- dwconv3x3 + Gram + norms + v (double-buffered halo, fp16 pre) ----------------
__device__ __forceinline__ float4 dw_quad(const float* hb, const float* wr) {
    float r4[4][4];
#pragma unroll
    for (int r = 0; r < 4; r++) {
        float2 a  = *reinterpret_cast<const float2*>(hb + r * 20);
        float2 b2 = *reinterpret_cast<const float2*>(hb + r * 20 + 2);
        r4[r][0] = a.x; r4[r][1] = a.y; r4[r][2] = b2.x; r4[r][3] = b2.y;
    }
    float ox = 0.f, oy = 0.f, oz = 0.f, ow = 0.f;
#pragma unroll
    for (int i2 = 0; i2 < 3; i2++)
#pragma unroll
        for (int j2 = 0; j2 < 3; j2++) {
            float wv = wr[i2 * 3 + j2];
            ox += r4[i2][j2]     * wv;
            oy += r4[i2][j2 + 1] * wv;
            oz += r4[i2 + 1][j2] * wv;
            ow += r4[i2 + 1][j2 + 1] * wv;
        }
    return make_float4(ox, oy, oz, ow);
}

// smem: halo[2*2880] + qs[24*QP2] + ks[24*QP2] = 72960 B -> 3 CTAs/SM
__global__ __launch_bounds__(256, 3) void dw_reduce_kernel(
    const __half* __restrict__ pre, const float* __restrict__ wq_dw,
    const float* __restrict__ wkv_dw,
    __half* __restrict__ vout, float* __restrict__ ssq, float* __restrict__ ssk,
    float* __restrict__ gram)
{
    extern __shared__ float sm[];
    float* halo = sm;                  // 2 x 2880 floats
    float* qs   = sm + 5760;
    float* ks   = qs + 24 * QP2;

    const int tid = threadIdx.x;
    const int b   = blockIdx.z >> 3;
    const int h   = blockIdx.z & 7;
    const int cb  = h * CH;
    const int tx0 = blockIdx.x * 16;
    const int ty0 = blockIdx.y * 16;

    const int cs = tid >> 6;
    const int qd = tid & 63;
    const int qy = qd >> 3, qx = qd & 7;
    const int hoff = (2 * qy) * 20 + 2 * qx;

    const __half* base = pre + (size_t)b * 3 * CDIM * HWSZ;

    int goff[11], hloc[11];
    bool val[11];
#pragma unroll
    for (int j = 0; j < 11; j++) {
        int i = tid + j * 256;
        if (i < 2592) {
            int ch  = i / 324;
            int rem = i - ch * 324;
            int rr  = rem / 18;
            int ccx = rem - rr * 18;
            int gy = ty0 - 1 + rr, gx = tx0 - 1 + ccx;
            val[j]  = ((unsigned)gy < 256u) && ((unsigned)gx < 256u);
            goff[j] = ch * HWSZ + gy * 256 + gx;
            hloc[j] = ch * 360 + rr * 20 + ccx;
        } else { val[j] = false; goff[j] = 0; hloc[j] = -1; }
    }

    {
        const __half* s0 = base + (size_t)cb * HWSZ;
#pragma unroll
        for (int j = 0; j < 11; j++)
            if (hloc[j] >= 0)
                halo[hloc[j]] = val[j] ? __half2float(__ldg(s0 + goff[j])) : 0.f;
    }
    __syncthreads();

    float rn[11];
#pragma unroll 1
    for (int g = 0; g < 9; g++) {
        const int t  = g / 3;
        const int sg = g - t * 3;

        if (g < 8) {
            int gn = g + 1, tn = gn / 3, sgn = gn - tn * 3;
            const __half* sn = base + (size_t)(tn * CDIM + cb + sgn * 8) * HWSZ;
#pragma unroll
            for (int j = 0; j < 11; j++)
                rn[j] = (hloc[j] >= 0 && val[j]) ? __half2float(__ldg(sn + goff[j])) : 0.f;
        }

        const float* hb = halo + (g & 1) * 2880;
#pragma unroll
        for (int it = 0; it < 2; it++) {
            int cc = cs + it * 4;
            int c  = sg * 8 + cc;
            const float* w = (t == 0) ? wq_dw + (size_t)(cb + c) * 9
                           : (t == 1) ? wkv_dw + (size_t)(cb + c) * 9
                                      : wkv_dw + (size_t)(CDIM + cb + c) * 9;
            float wr[9];
#pragma unroll
            for (int j = 0; j < 9; j++) wr[j] = __ldg(w + j);
            float4 o = dw_quad(hb + cc * 360 + hoff, wr);
            if (t == 0) {
                *reinterpret_cast<float4*>(qs + c * QP2 + qd * 4) = o;
            } else if (t == 1) {
                *reinterpret_cast<float4*>(ks + c * QP2 + qd * 4) = o;
            } else {
                __half* dst = vout + ((size_t)b * CDIM + cb + c) * HWSZ
                            + (ty0 + 2 * qy) * 256 + (tx0 + 2 * qx);
                uint32_t p0w = (uint32_t)__half_as_ushort(__float2half_rn(o.x))
                             | ((uint32_t)__half_as_ushort(__float2half_rn(o.y)) << 16);
                uint32_t p1w = (uint32_t)__half_as_ushort(__float2half_rn(o.z))
                             | ((uint32_t)__half_as_ushort(__float2half_rn(o.w)) << 16);
                *reinterpret_cast<uint32_t*>(dst)       = p0w;
                *reinterpret_cast<uint32_t*>(dst + 256) = p1w;
            }
        }

        if (g < 8) {
            float* hn = halo + ((g + 1) & 1) * 2880;
#pragma unroll
            for (int j = 0; j < 11; j++)
                if (hloc[j] >= 0) hn[hloc[j]] = rn[j];
        }
        __syncthreads();
    }

    // ---- sum of squares ----
    if (tid < 192) {
        int c = tid >> 3, s = tid & 7;
        float sq = 0.f, sk = 0.f;
#pragma unroll
        for (int i = 0; i < 8; i++) {
            int j = s + (i << 3);
            float4 a = *reinterpret_cast<const float4*>(qs + c * QP2 + 4 * j);
            sq += a.x * a.x + a.y * a.y + a.z * a.z + a.w * a.w;
            float4 kk = *reinterpret_cast<const float4*>(ks + c * QP2 + 4 * j);
            sk += kk.x * kk.x + kk.y * kk.y + kk.z * kk.z + kk.w * kk.w;
        }
#pragma unroll
        for (int off = 1; off < 8; off <<= 1) {
            sq += __shfl_xor_sync(0xffffffffu, sq, off);
            sk += __shfl_xor_sync(0xffffffffu, sk, off);
        }
        if (s == 0) {
            atomicAdd(&ssq[b * CDIM + cb + c], sq);
            atomicAdd(&ssk[b * CDIM + cb + c], sk);
        }
    }

    // ---- Gram ----
#pragma unroll 1
    for (int t = tid; t < 288; t += 256) {
        int e = t >> 3, s = t & 7;
        int c0 = (e / 6) * 4, d0 = (e % 6) * 4;
        float acc[16];
#pragma unroll
        for (int j = 0; j < 16; j++) acc[j] = 0.f;
#pragma unroll 2
        for (int i = 0; i < 8; i++) {
            int j = s + (i << 3);
            float4 qv[4], kv[4];
#pragma unroll
            for (int r = 0; r < 4; r++) {
                qv[r] = *reinterpret_cast<const float4*>(qs + (c0 + r) * QP2 + 4 * j);
                kv[r] = *reinterpret_cast<const float4*>(ks + (d0 + r) * QP2 + 4 * j);
            }
#pragma unroll
            for (int a = 0; a < 4; a++)
#pragma unroll
                for (int d = 0; d < 4; d++)
                    acc[a * 4 + d] += qv[a].x * kv[d].x + qv[a].y * kv[d].y
                                    + qv[a].z * kv[d].z + qv[a].w * kv[d].w;
        }
#pragma unroll
        for (int off = 1; off < 8; off <<= 1)
#pragma unroll
            for (int j = 0; j < 16; j++)
                acc[j] += __shfl_xor_sync(0xffffffffu, acc[j], off);
        if (s == 0) {
            float* gb = gram + (((size_t)b * NHEADS + h) * CH + c0) * CH + d0;
#pragma unroll
            for (int jq = 0; jq < 4; jq++)
#pragma unroll
                for (int jk = 0; jk < 4; jk++)
                    atomicAdd(&gb[jq * CH + jk], acc[jq * 4 + jk]);
        }
    }
}

// ---------------- softmax + M = Wproj * blockdiag(attn)  -> fp16 directly ----------------
__global__ __launch_bounds__(256) void attn_proj_kernel(
    const float* __restrict__ gram, const float* __restrict__ ssq,
    const float* __restrict__ ssk,  const float* __restrict__ temp,
    const float* __restrict__ wproj, __half* __restrict__ Mout)
{
    __shared__ float at[192][25];
    __shared__ float nk_s[192];
    const int b = blockIdx.x, tid = threadIdx.x;

    if (tid < 192) nk_s[tid] = fmaxf(sqrtf(ssk[b * CDIM + tid]), 1e-12f);
    __syncthreads();

    if (tid < 192) {
        int h = tid / 24, c = tid % 24;
        float nq = fmaxf(sqrtf(ssq[b * CDIM + tid]), 1e-12f);
        float tv = temp[h];
        const float* gr = gram + (((size_t)b * NHEADS + h) * CH + c) * CH;
        float vals[24];
        float mx = -1e30f;
#pragma unroll
        for (int d = 0; d < 24; d++) {
            float v = gr[d] / (nq * nk_s[h * 24 + d]) * tv;
            vals[d] = v;
            mx = fmaxf(mx, v);
        }
        float s = 0.f;
#pragma unroll
        for (int d = 0; d < 24; d++) { vals[d] = expf(vals[d] - mx); s += vals[d]; }
        float inv = 1.f / s;
#pragma unroll
        for (int d = 0; d < 24; d++) at[tid][d] = vals[d] * inv;
    }
    __syncthreads();

    for (int idx = tid; idx < 192 * 192; idx += 256) {
        int o = idx / 192, dg = idx % 192;
        int h = dg / 24, d = dg % 24;
        float s = 0.f;
#pragma unroll
        for (int c = 0; c < 24; c++)
            s += wproj[o * 192 + h * 24 + c] * at[h * 24 + c][d];
        Mout[(size_t)b * CDIM * CDIM + idx] = __float2half_rn(s);
    }
}

// ---------------- launch ----------------
extern "C" void kernel_launch(void* const* d_in, const int* in_sizes, int n_in,
                              void* d_out, int out_size) {
    const float* x      = (const float*)d_in[0];
    const float* x_ref  = (const float*)d_in[1];
    const float* wq     = (const float*)d_in[2];
    const float* wq_dw  = (const float*)d_in[3];
    const float* wkv    = (const float*)d_in[4];
    const float* wkv_dw = (const float*)d_in[5];
    const float* wproj  = (const float*)d_in[6];
    const float* temp   = (const float*)d_in[7];
    float* out = (float*)d_out;

    float *gram, *ssq, *ssk;
    __half *pre, *vh, *wqkv, *whm;
    cudaGetSymbolAddress((void**)&pre,  g_pre);
    cudaGetSymbolAddress((void**)&vh,   g_vh);
    cudaGetSymbolAddress((void**)&gram, g_gram);
    cudaGetSymbolAddress((void**)&ssq,  g_ssq);
    cudaGetSymbolAddress((void**)&ssk,  g_ssk);
    cudaGetSymbolAddress((void**)&wqkv, g_wqkv);
    cudaGetSymbolAddress((void**)&whm,  g_whm);

    const int smem2 = (5760 + 2 * 24 * QP2) * (int)sizeof(float);   // 72960 B
    cudaFuncSetAttribute(dw_reduce_kernel,
                         cudaFuncAttributeMaxDynamicSharedMemorySize, smem2);
    cudaFuncSetAttribute(hmma_gemm_kernel,
                         cudaFuncAttributeMaxDynamicSharedMemorySize, GEMM_SMEM);
    cudaFuncSetAttribute(hmma_gemm_h_kernel,
                         cudaFuncAttributeMaxDynamicSharedMemorySize, GEMM_SMEM_H);

    zero_stats_kernel<<<36, 256>>>(gram, ssq, ssk);

    // W -> fp16: wq into slot 0, wkv into slots 1,2
    w2f16_kernel<<<dim3(144, 1, 1), 256>>>(wq,  0LL, CDIM * CDIM, wqkv, 0LL);
    w2f16_kernel<<<dim3(288, 1, 1), 256>>>(wkv, 0LL, 2 * CDIM * CDIM,
                                           wqkv + CDIM * CDIM, 0LL);

    // pre (q | kv), fp16 contiguous scratch
    hmma_gemm_kernel<<<dim3(1024, 1, BSZ), 256, GEMM_SMEM>>>(
        x, (long long)CDIM * HWSZ, wqkv, 0LL,
        pre, (long long)3 * CDIM * HWSZ);
    hmma_gemm_kernel<<<dim3(1024, 2, BSZ), 256, GEMM_SMEM>>>(
        x_ref, (long long)CDIM * HWSZ, wqkv + CDIM * CDIM, 0LL,
        pre + (size_t)CDIM * HWSZ, (long long)3 * CDIM * HWSZ);

    dw_reduce_kernel<<<dim3(16, 16, BSZ * NHEADS), 256, smem2>>>(
        pre, wq_dw, wkv_dw, vh, ssq, ssk, gram);

    // softmax + projection fold, M written directly in fp16
    attn_proj_kernel<<<BSZ, 256>>>(gram, ssq, ssk, temp, wproj, whm);

    // out = M_b @ v  (1-pass fp16 GEMM, fp32 out)
    hmma_gemm_h_kernel<<<dim3(1024, 1, BSZ), 256, GEMM_SMEM_H>>>(
        vh, (long long)CDIM * HWSZ, whm, (long long)CDIM * CDIM,
        out, (long long)CDIM * HWSZ);
}

// round 17
// speedup vs baseline: 1.3632x; 1.0433x over previous
#include <cuda_runtime.h>
#include <cuda_fp16.h>
#include <cstdint>

#define HWSZ  65536
#define CDIM  192
#define NHEADS 8
#define CH    24
#define BSZ   2
#define QP2   260

// ---------------- scratch (no cudaMalloc allowed) ----------------
__device__ __half g_pre [(size_t)BSZ * 3 * CDIM * HWSZ];   // q | k | v-pre (fp16)
__device__ __half g_vh  [(size_t)BSZ * CDIM     * HWSZ];   // v in fp16
__device__ float  g_gram[BSZ * NHEADS * CH * CH];
__device__ float  g_ssq [BSZ * CDIM];
__device__ float  g_ssk [BSZ * CDIM];

// fp16 weights: slot 0 = wq, slots 1,2 = wkv   (row-major [rows][192])
__device__ __half g_wqkv[3 * CDIM * CDIM];
__device__ __half g_whm [BSZ * CDIM * CDIM];

__device__ __forceinline__ uint32_t smem_u32(const void* p) {
    uint32_t a;
    asm("{ .reg .u64 t; cvta.to.shared.u64 t, %1; cvt.u32.u64 %0, t; }" : "=r"(a) : "l"(p));
    return a;
}
__device__ __forceinline__ void cpa16(uint32_t dst, const void* src) {
    asm volatile("cp.async.cg.shared.global [%0], [%1], 16;" :: "r"(dst), "l"(src));
}
#define CPA_COMMIT() asm volatile("cp.async.commit_group;" ::: "memory")
#define CPA_WAIT(n)  asm volatile("cp.async.wait_group %0;" :: "n"(n) : "memory")

// ---------------- zero accumulators ----------------
__global__ void zero_stats_kernel(float* gram, float* ssq, float* ssk) {
    int i = blockIdx.x * 256 + threadIdx.x;
    if (i < BSZ * NHEADS * CH * CH) gram[i] = 0.f;
    if (i < BSZ * CDIM) { ssq[i] = 0.f; ssk[i] = 0.f; }
}

// ---------------- prep: fp32 W -> fp16 ----------------
__global__ void w2f16_kernel(const float* __restrict__ W, long long wstride_b,
                             int total, __half* __restrict__ out, long long ostride_b) {
    int b = blockIdx.z;
    int i = blockIdx.x * 256 + threadIdx.x;
    if (i >= total) return;
    out[(size_t)b * ostride_b + i] = __float2half_rn(W[(size_t)b * wstride_b + i]);
}

// ================= 1-pass HMMA fp16 GEMM, BK=32, fp32 X in, fp16 out =================
#define AST 40
#define BST 72
#define OFF_W(s)  ((s) * 7680)
#define OFF_X(s)  (23040 + (s) * 2304)
#define GEMM_SMEM ((23040 + 2 * 2304) * 2)   // 55296 B

__global__ __launch_bounds__(256, 2) void hmma_gemm_kernel(
    const float* __restrict__ X, long long xstride_b,
    const __half* __restrict__ Wh, long long wstride_b,
    __half* __restrict__ Y, long long ystride_b)
{
    extern __shared__ __half sms[];
    const uint32_t sb = smem_u32(sms);

    const int tid = threadIdx.x;
    const int lid = tid & 31;
    const int wid = tid >> 5;
    const int wm  = wid >> 1;
    const int wn  = wid & 1;
    const int p0  = blockIdx.x * 64;
    const int nt  = blockIdx.y;
    const int b   = blockIdx.z;

    const float* Xb = X + (size_t)b * xstride_b + p0;
    const __half* WhB = Wh + (size_t)b * wstride_b + (size_t)nt * 192 * 192;

    float acc[3][4][4];
#pragma unroll
    for (int i = 0; i < 3; i++)
#pragma unroll
        for (int j = 0; j < 4; j++)
#pragma unroll
            for (int r = 0; r < 4; r++) acc[i][j][r] = 0.f;

    const int xrow = tid >> 4, xc4 = (tid & 15) << 2;
    const int arow = (lid & 7) + ((lid >> 3) & 1) * 8;
    const int acol = (lid >> 4) * 8;
    const int brow = arow;
    const int bcoff = ((lid >> 4) & 1) * 8;

#pragma unroll
    for (int s = 0; s < 2; s++) {
#pragma unroll
        for (int j = 0; j < 3; j++) {
            int idx = tid + j * 256;
            int row = idx >> 2;
            int c8  = (idx & 3) << 3;
            cpa16(sb + (uint32_t)((OFF_W(s) + row * AST + c8) * 2),
                  WhB + (size_t)row * 192 + s * 32 + c8);
        }
        CPA_COMMIT();
    }
    float4 xv0 = *reinterpret_cast<const float4*>(Xb + (size_t)xrow * HWSZ + xc4);
    float4 xv1 = *reinterpret_cast<const float4*>(Xb + (size_t)(xrow + 16) * HWSZ + xc4);

#pragma unroll 1
    for (int it = 0; it < 6; it++) {
        const int ws = it % 3;
        const int xs = it & 1;

        // STS X(it): rows xrow, xrow+16; fp16 hi only
#pragma unroll
        for (int hlf = 0; hlf < 2; hlf++) {
            float4 v = hlf ? xv1 : xv0;
            int row = xrow + hlf * 16;
            uint32_t h01 = (uint32_t)__half_as_ushort(__float2half_rn(v.x))
                         | ((uint32_t)__half_as_ushort(__float2half_rn(v.y)) << 16);
            uint32_t h23 = (uint32_t)__half_as_ushort(__float2half_rn(v.z))
                         | ((uint32_t)__half_as_ushort(__float2half_rn(v.w)) << 16);
            uint32_t xa = sb + (uint32_t)((OFF_X(xs) + row * BST + xc4) * 2);
            asm volatile("st.shared.v2.u32 [%0], {%1, %2};" :: "r"(xa), "r"(h01), "r"(h23));
        }

        if (it < 5) { CPA_WAIT(1); } else { CPA_WAIT(0); }
        __syncthreads();

        if (it < 4) {
            int s = it + 2, ss = s % 3;
#pragma unroll
            for (int j = 0; j < 3; j++) {
                int idx = tid + j * 256;
                int row = idx >> 2;
                int c8  = (idx & 3) << 3;
                cpa16(sb + (uint32_t)((OFF_W(ss) + row * AST + c8) * 2),
                      WhB + (size_t)row * 192 + s * 32 + c8);
            }
            CPA_COMMIT();
        }
        if (it < 5) {
            xv0 = *reinterpret_cast<const float4*>(
                Xb + (size_t)((it + 1) * 32 + xrow) * HWSZ + xc4);
            xv1 = *reinterpret_cast<const float4*>(
                Xb + (size_t)((it + 1) * 32 + xrow + 16) * HWSZ + xc4);
        }

        uint32_t ah[2][3][4], bh[2][2][4];
#pragma unroll
        for (int kh = 0; kh < 2; kh++) {
#pragma unroll
            for (int mi = 0; mi < 3; mi++) {
                int r = wm * 48 + mi * 16 + arow;
                uint32_t addr = sb + (uint32_t)((OFF_W(ws) + r * AST + kh * 16 + acol) * 2);
                asm volatile("ldmatrix.sync.aligned.m8n8.x4.shared.b16 {%0,%1,%2,%3}, [%4];"
                    : "=r"(ah[kh][mi][0]), "=r"(ah[kh][mi][1]),
                      "=r"(ah[kh][mi][2]), "=r"(ah[kh][mi][3]) : "r"(addr));
            }
#pragma unroll
            for (int blk = 0; blk < 2; blk++) {
                int col = wn * 32 + blk * 16 + bcoff;
                int krow = kh * 16 + brow;
                uint32_t addr = sb + (uint32_t)((OFF_X(xs) + krow * BST + col) * 2);
                asm volatile("ldmatrix.sync.aligned.m8n8.x4.trans.shared.b16 {%0,%1,%2,%3}, [%4];"
                    : "=r"(bh[kh][blk][0]), "=r"(bh[kh][blk][1]),
                      "=r"(bh[kh][blk][2]), "=r"(bh[kh][blk][3]) : "r"(addr));
            }
        }

#define MMA(C, A, B0, B1) \
    asm volatile("mma.sync.aligned.m16n8k16.row.col.f32.f16.f16.f32 " \
        "{%0,%1,%2,%3}, {%4,%5,%6,%7}, {%8,%9}, {%0,%1,%2,%3};" \
        : "+f"((C)[0]), "+f"((C)[1]), "+f"((C)[2]), "+f"((C)[3]) \
        : "r"((A)[0]), "r"((A)[1]), "r"((A)[2]), "r"((A)[3]), "r"(B0), "r"(B1))

#pragma unroll
        for (int kh = 0; kh < 2; kh++)
#pragma unroll
            for (int mi = 0; mi < 3; mi++)
#pragma unroll
                for (int ni = 0; ni < 4; ni++) {
                    int blk = ni >> 1, hf = (ni & 1) << 1;
                    MMA(acc[mi][ni], ah[kh][mi], bh[kh][blk][hf], bh[kh][blk][hf + 1]);
                }
        __syncthreads();
    }

    __half* Yb = Y + (size_t)b * ystride_b + (size_t)nt * 192 * HWSZ + p0;
#pragma unroll
    for (int mi = 0; mi < 3; mi++) {
        int r0 = wm * 48 + mi * 16 + (lid >> 2);
#pragma unroll
        for (int ni = 0; ni < 4; ni++) {
            int px = wn * 32 + ni * 8 + (lid & 3) * 2;
            uint32_t w0 = (uint32_t)__half_as_ushort(__float2half_rn(acc[mi][ni][0]))
                        | ((uint32_t)__half_as_ushort(__float2half_rn(acc[mi][ni][1])) << 16);
            uint32_t w1 = (uint32_t)__half_as_ushort(__float2half_rn(acc[mi][ni][2]))
                        | ((uint32_t)__half_as_ushort(__float2half_rn(acc[mi][ni][3])) << 16);
            *reinterpret_cast<uint32_t*>(Yb + (size_t)r0 * HWSZ + px)       = w0;
            *reinterpret_cast<uint32_t*>(Yb + (size_t)(r0 + 8) * HWSZ + px) = w1;
        }
    }
}

// ================= 1-pass HMMA GEMM, fp16 X, fp32 out (out = M @ v) =================
#define GEMM_SMEM_H GEMM_SMEM

__global__ __launch_bounds__(256, 2) void hmma_gemm_h_kernel(
    const __half* __restrict__ X, long long xstride_b,
    const __half* __restrict__ Wh, long long wstride_b,
    float* __restrict__ Y, long long ystride_b)
{
    extern __shared__ __half sms[];
    const uint32_t sb = smem_u32(sms);

    const int tid = threadIdx.x;
    const int lid = tid & 31;
    const int wid = tid >> 5;
    const int wm  = wid >> 1;
    const int wn  = wid & 1;
    const int p0  = blockIdx.x * 64;
    const int b   = blockIdx.z;

    const __half* Xb = X + (size_t)b * xstride_b + p0;
    const __half* WhB = Wh + (size_t)b * wstride_b;

    float acc[3][4][4];
#pragma unroll
    for (int i = 0; i < 3; i++)
#pragma unroll
        for (int j = 0; j < 4; j++)
#pragma unroll
            for (int r = 0; r < 4; r++) acc[i][j][r] = 0.f;

    const int xrow = tid >> 3, xc8 = (tid & 7) << 3;
    const int arow = (lid & 7) + ((lid >> 3) & 1) * 8;
    const int acol = (lid >> 4) * 8;
    const int brow = arow;
    const int bcoff = ((lid >> 4) & 1) * 8;

#pragma unroll
    for (int s = 0; s < 2; s++) {
#pragma unroll
        for (int j = 0; j < 3; j++) {
            int idx = tid + j * 256;
            int row = idx >> 2;
            int c8  = (idx & 3) << 3;
            cpa16(sb + (uint32_t)((OFF_W(s) + row * AST + c8) * 2),
                  WhB + (size_t)row * 192 + s * 32 + c8);
        }
        CPA_COMMIT();
    }
    uint4 xv = *reinterpret_cast<const uint4*>(Xb + (size_t)xrow * HWSZ + xc8);

#pragma unroll 1
    for (int it = 0; it < 6; it++) {
        const int ws = it % 3;
        const int xs = it & 1;

        {
            uint32_t xa = sb + (uint32_t)((OFF_X(xs) + xrow * BST + xc8) * 2);
            asm volatile("st.shared.v4.u32 [%0], {%1, %2, %3, %4};"
                :: "r"(xa), "r"(xv.x), "r"(xv.y), "r"(xv.z), "r"(xv.w));
        }

        if (it < 5) { CPA_WAIT(1); } else { CPA_WAIT(0); }
        __syncthreads();

        if (it < 4) {
            int s = it + 2, ss = s % 3;
#pragma unroll
            for (int j = 0; j < 3; j++) {
                int idx = tid + j * 256;
                int row = idx >> 2;
                int c8  = (idx & 3) << 3;
                cpa16(sb + (uint32_t)((OFF_W(ss) + row * AST + c8) * 2),
                      WhB + (size_t)row * 192 + s * 32 + c8);
            }
            CPA_COMMIT();
        }
        if (it < 5)
            xv = *reinterpret_cast<const uint4*>(
                Xb + (size_t)((it + 1) * 32 + xrow) * HWSZ + xc8);

        uint32_t ah[2][3][4], bh[2][2][4];
#pragma unroll
        for (int kh = 0; kh < 2; kh++) {
#pragma unroll
            for (int mi = 0; mi < 3; mi++) {
                int r = wm * 48 + mi * 16 + arow;
                uint32_t addr = sb + (uint32_t)((OFF_W(ws) + r * AST + kh * 16 + acol) * 2);
                asm volatile("ldmatrix.sync.aligned.m8n8.x4.shared.b16 {%0,%1,%2,%3}, [%4];"
                    : "=r"(ah[kh][mi][0]), "=r"(ah[kh][mi][1]),
                      "=r"(ah[kh][mi][2]), "=r"(ah[kh][mi][3]) : "r"(addr));
            }
#pragma unroll
            for (int blk = 0; blk < 2; blk++) {
                int col = wn * 32 + blk * 16 + bcoff;
                int krow = kh * 16 + brow;
                uint32_t addr = sb + (uint32_t)((OFF_X(xs) + krow * BST + col) * 2);
                asm volatile("ldmatrix.sync.aligned.m8n8.x4.trans.shared.b16 {%0,%1,%2,%3}, [%4];"
                    : "=r"(bh[kh][blk][0]), "=r"(bh[kh][blk][1]),
                      "=r"(bh[kh][blk][2]), "=r"(bh[kh][blk][3]) : "r"(addr));
            }
        }

#pragma unroll
        for (int kh = 0; kh < 2; kh++)
#pragma unroll
            for (int mi = 0; mi < 3; mi++)
#pragma unroll
                for (int ni = 0; ni < 4; ni++) {
                    int blk = ni >> 1, hf = (ni & 1) << 1;
                    MMA(acc[mi][ni], ah[kh][mi], bh[kh][blk][hf], bh[kh][blk][hf + 1]);
                }
        __syncthreads();
    }

    float* Yb = Y + (size_t)b * ystride_b + p0;
#pragma unroll
    for (int mi = 0; mi < 3; mi++) {
        int r0 = wm * 48 + mi * 16 + (lid >> 2);
#pragma unroll
        for (int ni = 0; ni < 4; ni++) {
            int px = wn * 32 + ni * 8 + (lid & 3) * 2;
            *reinterpret_cast<float2*>(Yb + (size_t)r0 * HWSZ + px) =
                make_float2(acc[mi][ni][0], acc[mi][ni][1]);
            *reinterpret_cast<float2*>(Yb + (size_t)(r0 + 8) * HWSZ + px) =
                make_float2(acc[mi][ni][2], acc[mi][ni][3]);
        }
    }
}

// ---------------- dwconv3x3 + Gram + norms + v (double-buffered halo, fp16 pre) ----------------
__device__ __forceinline__ float4 dw_quad(const float* hb, const float* wr) {
    float r4[4][4];
#pragma unroll
    for (int r = 0; r < 4; r++) {
        float2 a  = *reinterpret_cast<const float2*>(hb + r * 20);
        float2 b2 = *reinterpret_cast<const float2*>(hb + r * 20 + 2);
        r4[r][0] = a.x; r4[r][1] = a.y; r4[r][2] = b2.x; r4[r][3] = b2.y;
    }
    float ox = 0.f, oy = 0.f, oz = 0.f, ow = 0.f;
#pragma unroll
    for (int i2 = 0; i2 < 3; i2++)
#pragma unroll
        for (int j2 = 0; j2 < 3; j2++) {
            float wv = wr[i2 * 3 + j2];
            ox += r4[i2][j2]     * wv;
            oy += r4[i2][j2 + 1] * wv;
            oz += r4[i2 + 1][j2] * wv;
            ow += r4[i2 + 1][j2 + 1] * wv;
        }
    return make_float4(ox, oy, oz, ow);
}

// smem: halo[2*2880] + qs[24*QP2] + ks[24*QP2] = 72960 B -> 3 CTAs/SM
__global__ __launch_bounds__(256, 3) void dw_reduce_kernel(
    const __half* __restrict__ pre, const float* __restrict__ wq_dw,
    const float* __restrict__ wkv_dw,
    __half* __restrict__ vout, float* __restrict__ ssq, float* __restrict__ ssk,
    float* __restrict__ gram)
{
    extern __shared__ float sm[];
    float* halo = sm;
    float* qs   = sm + 5760;
    float* ks   = qs + 24 * QP2;

    const int tid = threadIdx.x;
    const int b   = blockIdx.z >> 3;
    const int h   = blockIdx.z & 7;
    const int cb  = h * CH;
    const int tx0 = blockIdx.x * 16;
    const int ty0 = blockIdx.y * 16;

    const int cs = tid >> 6;
    const int qd = tid & 63;
    const int qy = qd >> 3, qx = qd & 7;
    const int hoff = (2 * qy) * 20 + 2 * qx;

    const __half* base = pre + (size_t)b * 3 * CDIM * HWSZ;

    int goff[11], hloc[11];
    bool val[11];
#pragma unroll
    for (int j = 0; j < 11; j++) {
        int i = tid + j * 256;
        if (i < 2592) {
            int ch  = i / 324;
            int rem = i - ch * 324;
            int rr  = rem / 18;
            int ccx = rem - rr * 18;
            int gy = ty0 - 1 + rr, gx = tx0 - 1 + ccx;
            val[j]  = ((unsigned)gy < 256u) && ((unsigned)gx < 256u);
            goff[j] = ch * HWSZ + gy * 256 + gx;
            hloc[j] = ch * 360 + rr * 20 + ccx;
        } else { val[j] = false; goff[j] = 0; hloc[j] = -1; }
    }

    {
        const __half* s0 = base + (size_t)cb * HWSZ;
#pragma unroll
        for (int j = 0; j < 11; j++)
            if (hloc[j] >= 0)
                halo[hloc[j]] = val[j] ? __half2float(__ldg(s0 + goff[j])) : 0.f;
    }
    __syncthreads();

    float rn[11];
#pragma unroll 1
    for (int g = 0; g < 9; g++) {
        const int t  = g / 3;
        const int sg = g - t * 3;

        if (g < 8) {
            int gn = g + 1, tn = gn / 3, sgn = gn - tn * 3;
            const __half* sn = base + (size_t)(tn * CDIM + cb + sgn * 8) * HWSZ;
#pragma unroll
            for (int j = 0; j < 11; j++)
                rn[j] = (hloc[j] >= 0 && val[j]) ? __half2float(__ldg(sn + goff[j])) : 0.f;
        }

        const float* hb = halo + (g & 1) * 2880;
#pragma unroll
        for (int it = 0; it < 2; it++) {
            int cc = cs + it * 4;
            int c  = sg * 8 + cc;
            const float* w = (t == 0) ? wq_dw + (size_t)(cb + c) * 9
                           : (t == 1) ? wkv_dw + (size_t)(cb + c) * 9
                                      : wkv_dw + (size_t)(CDIM + cb + c) * 9;
            float wr[9];
#pragma unroll
            for (int j = 0; j < 9; j++) wr[j] = __ldg(w + j);
            float4 o = dw_quad(hb + cc * 360 + hoff, wr);
            if (t == 0) {
                *reinterpret_cast<float4*>(qs + c * QP2 + qd * 4) = o;
            } else if (t == 1) {
                *reinterpret_cast<float4*>(ks + c * QP2 + qd * 4) = o;
            } else {
                __half* dst = vout + ((size_t)b * CDIM + cb + c) * HWSZ
                            + (ty0 + 2 * qy) * 256 + (tx0 + 2 * qx);
                uint32_t p0w = (uint32_t)__half_as_ushort(__float2half_rn(o.x))
                             | ((uint32_t)__half_as_ushort(__float2half_rn(o.y)) << 16);
                uint32_t p1w = (uint32_t)__half_as_ushort(__float2half_rn(o.z))
                             | ((uint32_t)__half_as_ushort(__float2half_rn(o.w)) << 16);
                *reinterpret_cast<uint32_t*>(dst)       = p0w;
                *reinterpret_cast<uint32_t*>(dst + 256) = p1w;
            }
        }

        if (g < 8) {
            float* hn = halo + ((g + 1) & 1) * 2880;
#pragma unroll
            for (int j = 0; j < 11; j++)
                if (hloc[j] >= 0) hn[hloc[j]] = rn[j];
        }
        __syncthreads();
    }

    // ---- sum of squares ----
    if (tid < 192) {
        int c = tid >> 3, s = tid & 7;
        float sq = 0.f, sk = 0.f;
#pragma unroll
        for (int i = 0; i < 8; i++) {
            int j = s + (i << 3);
            float4 a = *reinterpret_cast<const float4*>(qs + c * QP2 + 4 * j);
            sq += a.x * a.x + a.y * a.y + a.z * a.z + a.w * a.w;
            float4 kk = *reinterpret_cast<const float4*>(ks + c * QP2 + 4 * j);
            sk += kk.x * kk.x + kk.y * kk.y + kk.z * kk.z + kk.w * kk.w;
        }
#pragma unroll
        for (int off = 1; off < 8; off <<= 1) {
            sq += __shfl_xor_sync(0xffffffffu, sq, off);
            sk += __shfl_xor_sync(0xffffffffu, sk, off);
        }
        if (s == 0) {
            atomicAdd(&ssq[b * CDIM + cb + c], sq);
            atomicAdd(&ssk[b * CDIM + cb + c], sk);
        }
    }

    // ---- Gram ----
#pragma unroll 1
    for (int t = tid; t < 288; t += 256) {
        int e = t >> 3, s = t & 7;
        int c0 = (e / 6) * 4, d0 = (e % 6) * 4;
        float acc[16];
#pragma unroll
        for (int j = 0; j < 16; j++) acc[j] = 0.f;
#pragma unroll 2
        for (int i = 0; i < 8; i++) {
            int j = s + (i << 3);
            float4 qv[4], kv[4];
#pragma unroll
            for (int r = 0; r < 4; r++) {
                qv[r] = *reinterpret_cast<const float4*>(qs + (c0 + r) * QP2 + 4 * j);
                kv[r] = *reinterpret_cast<const float4*>(ks + (d0 + r) * QP2 + 4 * j);
            }
#pragma unroll
            for (int a = 0; a < 4; a++)
#pragma unroll
                for (int d = 0; d < 4; d++)
                    acc[a * 4 + d] += qv[a].x * kv[d].x + qv[a].y * kv[d].y
                                    + qv[a].z * kv[d].z + qv[a].w * kv[d].w;
        }
#pragma unroll
        for (int off = 1; off < 8; off <<= 1)
#pragma unroll
            for (int j = 0; j < 16; j++)
                acc[j] += __shfl_xor_sync(0xffffffffu, acc[j], off);
        if (s == 0) {
            float* gb = gram + (((size_t)b * NHEADS + h) * CH + c0) * CH + d0;
#pragma unroll
            for (int jq = 0; jq < 4; jq++)
#pragma unroll
                for (int jk = 0; jk < 4; jk++)
                    atomicAdd(&gb[jq * CH + jk], acc[jq * 4 + jk]);
        }
    }
}

// ---------------- softmax + M = Wproj * blockdiag(attn)  -> fp16 directly ----------------
__global__ __launch_bounds__(256) void attn_proj_kernel(
    const float* __restrict__ gram, const float* __restrict__ ssq,
    const float* __restrict__ ssk,  const float* __restrict__ temp,
    const float* __restrict__ wproj, __half* __restrict__ Mout)
{
    __shared__ float at[192][25];
    __shared__ float nk_s[192];
    const int b = blockIdx.x, tid = threadIdx.x;

    if (tid < 192) nk_s[tid] = fmaxf(sqrtf(ssk[b * CDIM + tid]), 1e-12f);
    __syncthreads();

    if (tid < 192) {
        int h = tid / 24, c = tid % 24;
        float nq = fmaxf(sqrtf(ssq[b * CDIM + tid]), 1e-12f);
        float tv = temp[h];
        const float* gr = gram + (((size_t)b * NHEADS + h) * CH + c) * CH;
        float vals[24];
        float mx = -1e30f;
#pragma unroll
        for (int d = 0; d < 24; d++) {
            float v = gr[d] / (nq * nk_s[h * 24 + d]) * tv;
            vals[d] = v;
            mx = fmaxf(mx, v);
        }
        float s = 0.f;
#pragma unroll
        for (int d = 0; d < 24; d++) { vals[d] = expf(vals[d] - mx); s += vals[d]; }
        float inv = 1.f / s;
#pragma unroll
        for (int d = 0; d < 24; d++) at[tid][d] = vals[d] * inv;
    }
    __syncthreads();

    for (int idx = tid; idx < 192 * 192; idx += 256) {
        int o = idx / 192, dg = idx % 192;
        int h = dg / 24, d = dg % 24;
        float s = 0.f;
#pragma unroll
        for (int c = 0; c < 24; c++)
            s += wproj[o * 192 + h * 24 + c] * at[h * 24 + c][d];
        Mout[(size_t)b * CDIM * CDIM + idx] = __float2half_rn(s);
    }
}

// ---------------- launch ----------------
extern "C" void kernel_launch(void* const* d_in, const int* in_sizes, int n_in,
                              void* d_out, int out_size) {
    const float* x      = (const float*)d_in[0];
    const float* x_ref  = (const float*)d_in[1];
    const float* wq     = (const float*)d_in[2];
    const float* wq_dw  = (const float*)d_in[3];
    const float* wkv    = (const float*)d_in[4];
    const float* wkv_dw = (const float*)d_in[5];
    const float* wproj  = (const float*)d_in[6];
    const float* temp   = (const float*)d_in[7];
    float* out = (float*)d_out;

    float *gram, *ssq, *ssk;
    __half *pre, *vh, *wqkv, *whm;
    cudaGetSymbolAddress((void**)&pre,  g_pre);
    cudaGetSymbolAddress((void**)&vh,   g_vh);
    cudaGetSymbolAddress((void**)&gram, g_gram);
    cudaGetSymbolAddress((void**)&ssq,  g_ssq);
    cudaGetSymbolAddress((void**)&ssk,  g_ssk);
    cudaGetSymbolAddress((void**)&wqkv, g_wqkv);
    cudaGetSymbolAddress((void**)&whm,  g_whm);

    const int smem2 = (5760 + 2 * 24 * QP2) * (int)sizeof(float);   // 72960 B
    cudaFuncSetAttribute(dw_reduce_kernel,
                         cudaFuncAttributeMaxDynamicSharedMemorySize, smem2);
    cudaFuncSetAttribute(hmma_gemm_kernel,
                         cudaFuncAttributeMaxDynamicSharedMemorySize, GEMM_SMEM);
    cudaFuncSetAttribute(hmma_gemm_h_kernel,
                         cudaFuncAttributeMaxDynamicSharedMemorySize, GEMM_SMEM_H);

    zero_stats_kernel<<<36, 256>>>(gram, ssq, ssk);

    w2f16_kernel<<<dim3(144, 1, 1), 256>>>(wq,  0LL, CDIM * CDIM, wqkv, 0LL);
    w2f16_kernel<<<dim3(288, 1, 1), 256>>>(wkv, 0LL, 2 * CDIM * CDIM,
                                           wqkv + CDIM * CDIM, 0LL);

    hmma_gemm_kernel<<<dim3(1024, 1, BSZ), 256, GEMM_SMEM>>>(
        x, (long long)CDIM * HWSZ, wqkv, 0LL,
        pre, (long long)3 * CDIM * HWSZ);
    hmma_gemm_kernel<<<dim3(1024, 2, BSZ), 256, GEMM_SMEM>>>(
        x_ref, (long long)CDIM * HWSZ, wqkv + CDIM * CDIM, 0LL,
        pre + (size_t)CDIM * HWSZ, (long long)3 * CDIM * HWSZ);

    dw_reduce_kernel<<<dim3(16, 16, BSZ * NHEADS), 256, smem2>>>(
        pre, wq_dw, wkv_dw, vh, ssq, ssk, gram);

    attn_proj_kernel<<<BSZ, 256>>>(gram, ssq, ssk, temp, wproj, whm);

    hmma_gemm_h_kernel<<<dim3(1024, 1, BSZ), 256, GEMM_SMEM_H>>>(
        vh, (long long)CDIM * HWSZ, whm, (long long)CDIM * CDIM,
        out, (long long)CDIM * HWSZ);
}